// round 1
// baseline (speedup 1.0000x reference)
#include <cuda_runtime.h>

#define N_TOK 4096
#define D_MODEL 512
#define K_LR 256
#define H_HEADS 8
#define DHEAD 64
#define D_FF 2048
#define EPS_LN 1e-5f
#define ATTN_SCALE 0.125f   // 64^-0.5
#define NSPLIT 32

// ---------------- scratch (device globals: allocation-free) ----------------
__device__ float g_NR[N_TOK * D_MODEL];
__device__ float g_NI[N_TOK * D_MODEL];
__device__ float g_QR[N_TOK * D_MODEL];
__device__ float g_QI[N_TOK * D_MODEL];
__device__ float g_KR[N_TOK * D_MODEL];
__device__ float g_KI[N_TOK * D_MODEL];
__device__ float g_VR[N_TOK * D_MODEL];
__device__ float g_VI[N_TOK * D_MODEL];
__device__ float g_KPR[K_LR * D_MODEL];
__device__ float g_KPI[K_LR * D_MODEL];
__device__ float g_VPR[K_LR * D_MODEL];
__device__ float g_VPI[K_LR * D_MODEL];
__device__ float g_DR[(size_t)H_HEADS * N_TOK * K_LR];
__device__ float g_DI[(size_t)H_HEADS * N_TOK * K_LR];
__device__ float g_OR[N_TOK * D_MODEL];
__device__ float g_OI[N_TOK * D_MODEL];
__device__ float g_HR[N_TOK * D_FF];
__device__ float g_HI[N_TOK * D_FF];
__device__ float g_PSUM[(size_t)4 * NSPLIT * K_LR * D_MODEL];

// ---------------- block reduction ----------------
__device__ __forceinline__ float blockSum(float v, float* red) {
#pragma unroll
    for (int o = 16; o > 0; o >>= 1) v += __shfl_xor_sync(0xffffffffu, v, o);
    int lane = threadIdx.x & 31, w = threadIdx.x >> 5;
    if (lane == 0) red[w] = v;
    __syncthreads();
    if (w == 0) {
        float x = (lane < 16) ? red[lane] : 0.f;
#pragma unroll
        for (int o = 8; o > 0; o >>= 1) x += __shfl_xor_sync(0xffffffffu, x, o);
        if (lane == 0) red[0] = x;
    }
    __syncthreads();
    float r = red[0];
    __syncthreads();
    return r;
}

// ---------------- complex layernorm (whitening) ----------------
__global__ void cln_kernel(const float* __restrict__ xr, const float* __restrict__ xi,
                           float* __restrict__ nr, float* __restrict__ ni) {
    __shared__ float red[16];
    int row = blockIdx.x;
    int t = threadIdx.x;  // 512 threads, D_MODEL = 512
    long long base = (long long)row * D_MODEL;
    float vr = xr[base + t];
    float vi = xi[base + t];
    const float invD = 1.0f / D_MODEL;
    float mr = blockSum(vr, red) * invD;
    float mi = blockSum(vi, red) * invD;
    float cr = vr - mr, ci = vi - mi;
    float Crr = blockSum(cr * cr, red) * invD + EPS_LN;
    float Cii = blockSum(ci * ci, red) * invD + EPS_LN;
    float Cri = blockSum(cr * ci, red) * invD;
    float s = sqrtf(Crr * Cii - Cri * Cri);
    float tt = sqrtf(Cii + Crr + 2.0f * s);
    float inv = 1.0f / (s * tt);
    float Rrr = (Cii + s) * inv;
    float Rii = (Crr + s) * inv;
    float Rri = -Cri * inv;
    nr[base + t] = Rrr * cr + Rri * ci;
    ni[base + t] = Rii * ci + Rri * cr;
}

// ---------------- general SGEMM: C = beta*C + alpha*A@op(B) (+bias) ----------------
// A: [M,Kd] row-major (lda). B: TB? [N,Kd] (ldb) used transposed : [Kd,N] (ldb).
// Batched over blockIdx.z via element strides sA/sB/sC. M % 128 == 0, Kd % 8 == 0 assumed.
template <bool TB>
__global__ void gemm_kernel(const float* __restrict__ A, const float* __restrict__ B,
                            float* __restrict__ C,
                            int M, int N, int Kd, int lda, int ldb, int ldc,
                            long long sA, long long sB, long long sC,
                            float alpha, float beta, const float* __restrict__ bias) {
    __shared__ float As[8][132];
    __shared__ float Bs[8][132];
    const float* Ab = A + (long long)blockIdx.z * sA;
    const float* Bb = B + (long long)blockIdx.z * sB;
    float* Cb = C + (long long)blockIdx.z * sC;
    int brow = blockIdx.y * 128, bcol = blockIdx.x * 128;
    int tid = threadIdx.x;
    int trow = (tid >> 4) << 3, tcol = (tid & 15) << 3;
    float acc[8][8];
#pragma unroll
    for (int i = 0; i < 8; i++)
#pragma unroll
        for (int j = 0; j < 8; j++) acc[i][j] = 0.f;

    for (int k0 = 0; k0 < Kd; k0 += 8) {
#pragma unroll
        for (int i = 0; i < 4; i++) {
            int l = tid + i * 256;
            int m = l >> 3, k = l & 7;
            As[k][m] = Ab[(long long)(brow + m) * lda + (k0 + k)];
        }
        if (!TB) {
#pragma unroll
            for (int i = 0; i < 4; i++) {
                int l = tid + i * 256;
                int k = l >> 7, n = l & 127;
                int gn = bcol + n;
                Bs[k][n] = (gn < N) ? Bb[(long long)(k0 + k) * ldb + gn] : 0.f;
            }
        } else {
#pragma unroll
            for (int i = 0; i < 4; i++) {
                int l = tid + i * 256;
                int n = l >> 3, k = l & 7;
                int gn = bcol + n;
                Bs[k][n] = (gn < N) ? Bb[(long long)gn * ldb + (k0 + k)] : 0.f;
            }
        }
        __syncthreads();
#pragma unroll
        for (int kk = 0; kk < 8; kk++) {
            float4 a0 = *(const float4*)&As[kk][trow];
            float4 a1 = *(const float4*)&As[kk][trow + 4];
            float4 b0 = *(const float4*)&Bs[kk][tcol];
            float4 b1 = *(const float4*)&Bs[kk][tcol + 4];
            float av[8] = {a0.x, a0.y, a0.z, a0.w, a1.x, a1.y, a1.z, a1.w};
            float bv[8] = {b0.x, b0.y, b0.z, b0.w, b1.x, b1.y, b1.z, b1.w};
#pragma unroll
            for (int i = 0; i < 8; i++)
#pragma unroll
                for (int j = 0; j < 8; j++)
                    acc[i][j] = fmaf(av[i], bv[j], acc[i][j]);
        }
        __syncthreads();
    }
#pragma unroll
    for (int i = 0; i < 8; i++) {
        long long rowoff = (long long)(brow + trow + i) * ldc;
#pragma unroll
        for (int j = 0; j < 8; j++) {
            int gn = bcol + tcol + j;
            if (gn >= N) continue;
            float v = alpha * acc[i][j];
            if (beta != 0.f) v += Cb[rowoff + gn];
            if (bias) v += bias[gn];
            Cb[rowoff + gn] = v;
        }
    }
}

// ---------------- split-K projection: P[z] = (A^T @ B) over K-slice z ----------------
// A: [N_TOK, K_LR] (proj matrix), B: [N_TOK, D_MODEL]. Output P: [NSPLIT, K_LR, D_MODEL].
__global__ void proj_splitk_kernel(const float* __restrict__ A, const float* __restrict__ B,
                                   float* __restrict__ P) {
    __shared__ float As[8][132];
    __shared__ float Bs[8][132];
    const int lda = K_LR, ldb = D_MODEL;
    int z = blockIdx.z;
    const int chunk = N_TOK / NSPLIT;  // 128
    int kbeg = z * chunk;
    int brow = blockIdx.y * 128, bcol = blockIdx.x * 128;
    int tid = threadIdx.x;
    int trow = (tid >> 4) << 3, tcol = (tid & 15) << 3;
    float acc[8][8];
#pragma unroll
    for (int i = 0; i < 8; i++)
#pragma unroll
        for (int j = 0; j < 8; j++) acc[i][j] = 0.f;

    for (int k0 = kbeg; k0 < kbeg + chunk; k0 += 8) {
#pragma unroll
        for (int i = 0; i < 4; i++) {
            int l = tid + i * 256;
            int k = l >> 7, m = l & 127;
            As[k][m] = A[(long long)(k0 + k) * lda + brow + m];
        }
#pragma unroll
        for (int i = 0; i < 4; i++) {
            int l = tid + i * 256;
            int k = l >> 7, n = l & 127;
            Bs[k][n] = B[(long long)(k0 + k) * ldb + bcol + n];
        }
        __syncthreads();
#pragma unroll
        for (int kk = 0; kk < 8; kk++) {
            float4 a0 = *(const float4*)&As[kk][trow];
            float4 a1 = *(const float4*)&As[kk][trow + 4];
            float4 b0 = *(const float4*)&Bs[kk][tcol];
            float4 b1 = *(const float4*)&Bs[kk][tcol + 4];
            float av[8] = {a0.x, a0.y, a0.z, a0.w, a1.x, a1.y, a1.z, a1.w};
            float bv[8] = {b0.x, b0.y, b0.z, b0.w, b1.x, b1.y, b1.z, b1.w};
#pragma unroll
            for (int i = 0; i < 8; i++)
#pragma unroll
                for (int j = 0; j < 8; j++)
                    acc[i][j] = fmaf(av[i], bv[j], acc[i][j]);
        }
        __syncthreads();
    }
    float* Pz = P + (long long)z * K_LR * D_MODEL;
#pragma unroll
    for (int i = 0; i < 8; i++)
#pragma unroll
        for (int j = 0; j < 8; j++)
            Pz[(long long)(brow + trow + i) * D_MODEL + bcol + tcol + j] = acc[i][j];
}

__global__ void proj_reduce_kernel(const float* __restrict__ P,
                                   float* __restrict__ kpr, float* __restrict__ kpi,
                                   float* __restrict__ vpr, float* __restrict__ vpi) {
    const int n = K_LR * D_MODEL;
    int i = blockIdx.x * blockDim.x + threadIdx.x;
    if (i >= n) return;
    float* outs[4] = {kpr, kpi, vpr, vpi};
#pragma unroll
    for (int p = 0; p < 4; p++) {
        const float* base = P + (long long)p * NSPLIT * n + i;
        float s = 0.f;
#pragma unroll
        for (int z = 0; z < NSPLIT; z++) s += base[(long long)z * n];
        outs[p][i] = s;
    }
}

__global__ void relu2_kernel(float* __restrict__ a, float* __restrict__ b, int n) {
    int i = blockIdx.x * blockDim.x + threadIdx.x;
    int stride = gridDim.x * blockDim.x;
    for (; i < n; i += stride) {
        a[i] = fmaxf(a[i], 0.f);
        b[i] = fmaxf(b[i], 0.f);
    }
}

// ---------------- host launcher ----------------
static inline void gemmL(const float* A, const float* B, float* C,
                         int M, int N, int Kd, int lda, int ldb, int ldc,
                         long long sA, long long sB, long long sC, int batch,
                         float alpha, float beta, const float* bias, bool tb) {
    dim3 grid((N + 127) / 128, (M + 127) / 128, batch);
    if (tb)
        gemm_kernel<true><<<grid, 256>>>(A, B, C, M, N, Kd, lda, ldb, ldc, sA, sB, sC, alpha, beta, bias);
    else
        gemm_kernel<false><<<grid, 256>>>(A, B, C, M, N, Kd, lda, ldb, ldc, sA, sB, sC, alpha, beta, bias);
}

extern "C" void kernel_launch(void* const* d_in, const int* in_sizes, int n_in,
                              void* d_out, int out_size) {
    const float* x_real = (const float*)d_in[0];
    const float* x_imag = (const float*)d_in[1];
    const float* Wq = (const float*)d_in[2];
    const float* bq = (const float*)d_in[3];
    const float* Wk = (const float*)d_in[4];
    const float* bk = (const float*)d_in[5];
    const float* Wv = (const float*)d_in[6];
    const float* bv = (const float*)d_in[7];
    const float* pk = (const float*)d_in[8];
    const float* pv = (const float*)d_in[9];
    const float* Wout = (const float*)d_in[10];
    const float* bout = (const float*)d_in[11];
    const float* W1r = (const float*)d_in[12];
    const float* W1i = (const float*)d_in[13];
    const float* b1r = (const float*)d_in[14];
    const float* b1i = (const float*)d_in[15];
    const float* W2r = (const float*)d_in[16];
    const float* W2i = (const float*)d_in[17];
    const float* b2r = (const float*)d_in[18];
    const float* b2i = (const float*)d_in[19];

    float* xr = (float*)d_out;
    float* xi = xr + (size_t)N_TOK * D_MODEL;

    float *NR, *NI, *QR, *QI, *KR, *KI, *VR, *VI;
    float *KPR, *KPI, *VPR, *VPI, *DR, *DI, *ORr, *OIr, *HR, *HI, *PSUM;
    cudaGetSymbolAddress((void**)&NR, g_NR);
    cudaGetSymbolAddress((void**)&NI, g_NI);
    cudaGetSymbolAddress((void**)&QR, g_QR);
    cudaGetSymbolAddress((void**)&QI, g_QI);
    cudaGetSymbolAddress((void**)&KR, g_KR);
    cudaGetSymbolAddress((void**)&KI, g_KI);
    cudaGetSymbolAddress((void**)&VR, g_VR);
    cudaGetSymbolAddress((void**)&VI, g_VI);
    cudaGetSymbolAddress((void**)&KPR, g_KPR);
    cudaGetSymbolAddress((void**)&KPI, g_KPI);
    cudaGetSymbolAddress((void**)&VPR, g_VPR);
    cudaGetSymbolAddress((void**)&VPI, g_VPI);
    cudaGetSymbolAddress((void**)&DR, g_DR);
    cudaGetSymbolAddress((void**)&DI, g_DI);
    cudaGetSymbolAddress((void**)&ORr, g_OR);
    cudaGetSymbolAddress((void**)&OIr, g_OI);
    cudaGetSymbolAddress((void**)&HR, g_HR);
    cudaGetSymbolAddress((void**)&HI, g_HI);
    cudaGetSymbolAddress((void**)&PSUM, g_PSUM);

    const size_t ND_BYTES = (size_t)N_TOK * D_MODEL * sizeof(float);
    cudaMemcpyAsync(xr, x_real, ND_BYTES, cudaMemcpyDeviceToDevice, 0);
    cudaMemcpyAsync(xi, x_imag, ND_BYTES, cudaMemcpyDeviceToDevice, 0);

    const long long NK = (long long)N_TOK * K_LR;
    const long long PSZ = (long long)NSPLIT * K_LR * D_MODEL;

    for (int d = 0; d < 2; d++) {
        const float* Wq_d = Wq + (size_t)d * D_MODEL * D_MODEL;
        const float* bq_d = bq + (size_t)d * D_MODEL;
        const float* Wk_d = Wk + (size_t)d * D_MODEL * D_MODEL;
        const float* bk_d = bk + (size_t)d * D_MODEL;
        const float* Wv_d = Wv + (size_t)d * D_MODEL * D_MODEL;
        const float* bv_d = bv + (size_t)d * D_MODEL;
        const float* pk_d = pk + (size_t)d * N_TOK * K_LR;
        const float* pv_d = pv + (size_t)d * N_TOK * K_LR;
        const float* Wo_d = Wout + (size_t)d * D_MODEL * D_MODEL;
        const float* bo_d = bout + (size_t)d * D_MODEL;
        const float* W1r_d = W1r + (size_t)d * D_MODEL * D_FF;
        const float* W1i_d = W1i + (size_t)d * D_MODEL * D_FF;
        const float* b1r_d = b1r + (size_t)d * D_FF;
        const float* b1i_d = b1i + (size_t)d * D_FF;
        const float* W2r_d = W2r + (size_t)d * D_FF * D_MODEL;
        const float* W2i_d = W2i + (size_t)d * D_FF * D_MODEL;
        const float* b2r_d = b2r + (size_t)d * D_MODEL;
        const float* b2i_d = b2i + (size_t)d * D_MODEL;

        // ---- LN1
        cln_kernel<<<N_TOK, 512>>>(xr, xi, NR, NI);

        // ---- QKV (real weights applied to real & imag parts)
        gemmL(NR, Wq_d, QR, N_TOK, D_MODEL, D_MODEL, D_MODEL, D_MODEL, D_MODEL, 0, 0, 0, 1, 1.f, 0.f, bq_d, false);
        gemmL(NI, Wq_d, QI, N_TOK, D_MODEL, D_MODEL, D_MODEL, D_MODEL, D_MODEL, 0, 0, 0, 1, 1.f, 0.f, bq_d, false);
        gemmL(NR, Wk_d, KR, N_TOK, D_MODEL, D_MODEL, D_MODEL, D_MODEL, D_MODEL, 0, 0, 0, 1, 1.f, 0.f, bk_d, false);
        gemmL(NI, Wk_d, KI, N_TOK, D_MODEL, D_MODEL, D_MODEL, D_MODEL, D_MODEL, 0, 0, 0, 1, 1.f, 0.f, bk_d, false);
        gemmL(NR, Wv_d, VR, N_TOK, D_MODEL, D_MODEL, D_MODEL, D_MODEL, D_MODEL, 0, 0, 0, 1, 1.f, 0.f, bv_d, false);
        gemmL(NI, Wv_d, VI, N_TOK, D_MODEL, D_MODEL, D_MODEL, D_MODEL, D_MODEL, 0, 0, 0, 1, 1.f, 0.f, bv_d, false);

        // ---- low-rank projections (split-K, deterministic reduce)
        {
            dim3 g(D_MODEL / 128, K_LR / 128, NSPLIT);
            proj_splitk_kernel<<<g, 256>>>(pk_d, KR, PSUM + 0 * PSZ);
            proj_splitk_kernel<<<g, 256>>>(pk_d, KI, PSUM + 1 * PSZ);
            proj_splitk_kernel<<<g, 256>>>(pv_d, VR, PSUM + 2 * PSZ);
            proj_splitk_kernel<<<g, 256>>>(pv_d, VI, PSUM + 3 * PSZ);
            proj_reduce_kernel<<<(K_LR * D_MODEL + 255) / 256, 256>>>(PSUM, KPR, KPI, VPR, VPI);
        }

        // ---- complex dots per head (batched over z = head)
        gemmL(QR, KPR, DR, N_TOK, K_LR, DHEAD, D_MODEL, D_MODEL, K_LR, DHEAD, DHEAD, NK, H_HEADS, ATTN_SCALE, 0.f, nullptr, true);
        gemmL(QI, KPI, DR, N_TOK, K_LR, DHEAD, D_MODEL, D_MODEL, K_LR, DHEAD, DHEAD, NK, H_HEADS, -ATTN_SCALE, 1.f, nullptr, true);
        gemmL(QR, KPI, DI, N_TOK, K_LR, DHEAD, D_MODEL, D_MODEL, K_LR, DHEAD, DHEAD, NK, H_HEADS, ATTN_SCALE, 0.f, nullptr, true);
        gemmL(QI, KPR, DI, N_TOK, K_LR, DHEAD, D_MODEL, D_MODEL, K_LR, DHEAD, DHEAD, NK, H_HEADS, ATTN_SCALE, 1.f, nullptr, true);

        // ---- attn out per head
        gemmL(DR, VPR, ORr, N_TOK, DHEAD, K_LR, K_LR, D_MODEL, D_MODEL, NK, DHEAD, DHEAD, H_HEADS, 1.f, 0.f, nullptr, false);
        gemmL(DI, VPI, ORr, N_TOK, DHEAD, K_LR, K_LR, D_MODEL, D_MODEL, NK, DHEAD, DHEAD, H_HEADS, -1.f, 1.f, nullptr, false);
        gemmL(DR, VPI, OIr, N_TOK, DHEAD, K_LR, K_LR, D_MODEL, D_MODEL, NK, DHEAD, DHEAD, H_HEADS, 1.f, 0.f, nullptr, false);
        gemmL(DI, VPR, OIr, N_TOK, DHEAD, K_LR, K_LR, D_MODEL, D_MODEL, NK, DHEAD, DHEAD, H_HEADS, 1.f, 1.f, nullptr, false);

        // ---- output projection + residual (accumulate into state)
        gemmL(ORr, Wo_d, xr, N_TOK, D_MODEL, D_MODEL, D_MODEL, D_MODEL, D_MODEL, 0, 0, 0, 1, 1.f, 1.f, bo_d, false);
        gemmL(OIr, Wo_d, xi, N_TOK, D_MODEL, D_MODEL, D_MODEL, D_MODEL, D_MODEL, 0, 0, 0, 1, 1.f, 1.f, bo_d, false);

        // ---- LN2
        cln_kernel<<<N_TOK, 512>>>(xr, xi, NR, NI);

        // ---- complex FFN
        gemmL(NR, W1r_d, HR, N_TOK, D_FF, D_MODEL, D_MODEL, D_FF, D_FF, 0, 0, 0, 1, 1.f, 0.f, b1r_d, false);
        gemmL(NI, W1i_d, HR, N_TOK, D_FF, D_MODEL, D_MODEL, D_FF, D_FF, 0, 0, 0, 1, -1.f, 1.f, nullptr, false);
        gemmL(NR, W1i_d, HI, N_TOK, D_FF, D_MODEL, D_MODEL, D_FF, D_FF, 0, 0, 0, 1, 1.f, 0.f, b1i_d, false);
        gemmL(NI, W1r_d, HI, N_TOK, D_FF, D_MODEL, D_MODEL, D_FF, D_FF, 0, 0, 0, 1, 1.f, 1.f, nullptr, false);
        relu2_kernel<<<4096, 256>>>(HR, HI, N_TOK * D_FF);
        gemmL(HR, W2r_d, xr, N_TOK, D_MODEL, D_FF, D_FF, D_MODEL, D_MODEL, 0, 0, 0, 1, 1.f, 1.f, b2r_d, false);
        gemmL(HI, W2i_d, xr, N_TOK, D_MODEL, D_FF, D_FF, D_MODEL, D_MODEL, 0, 0, 0, 1, -1.f, 1.f, nullptr, false);
        gemmL(HR, W2i_d, xi, N_TOK, D_MODEL, D_FF, D_FF, D_MODEL, D_MODEL, 0, 0, 0, 1, 1.f, 1.f, b2i_d, false);
        gemmL(HI, W2r_d, xi, N_TOK, D_MODEL, D_FF, D_FF, D_MODEL, D_MODEL, 0, 0, 0, 1, 1.f, 1.f, nullptr, false);
    }
}

// round 3
// speedup vs baseline: 2.2517x; 2.2517x over previous
#include <cuda_runtime.h>
#include <cstdint>

#define N_TOK 4096
#define D_MODEL 512
#define K_LR 256
#define H_HEADS 8
#define DHEAD 64
#define D_FF 2048
#define EPS_LN 1e-5f
#define ATTN_SCALE 0.125f
#define NSPLIT 32
#define KT 16

// ---------------- scratch (device globals: allocation-free) ----------------
__device__ float g_NR[N_TOK * D_MODEL];
__device__ float g_NI[N_TOK * D_MODEL];
__device__ float g_QR[N_TOK * D_MODEL];
__device__ float g_QI[N_TOK * D_MODEL];
__device__ float g_KR[N_TOK * D_MODEL];
__device__ float g_KI[N_TOK * D_MODEL];
__device__ float g_VR[N_TOK * D_MODEL];
__device__ float g_VI[N_TOK * D_MODEL];
__device__ float g_KPR[K_LR * D_MODEL];
__device__ float g_KPI[K_LR * D_MODEL];
__device__ float g_VPR[K_LR * D_MODEL];
__device__ float g_VPI[K_LR * D_MODEL];
__device__ float g_DR[(size_t)H_HEADS * N_TOK * K_LR];
__device__ float g_DI[(size_t)H_HEADS * N_TOK * K_LR];
__device__ float g_OR[N_TOK * D_MODEL];
__device__ float g_OI[N_TOK * D_MODEL];
__device__ float g_HR[N_TOK * D_FF];
__device__ float g_HI[N_TOK * D_FF];
__device__ float g_PSUM[(size_t)4 * NSPLIT * K_LR * D_MODEL];

// ---------------- bf16 split helpers ----------------
// pack: element0 (k even) in LOW half, element1 in HIGH half.
__device__ __forceinline__ unsigned packbf(float x0, float x1) {
    unsigned r;
    asm("cvt.rn.bf16x2.f32 %0, %1, %2;" : "=r"(r) : "f"(x1), "f"(x0));
    return r;
}
__device__ __forceinline__ void split2(float x0, float x1, unsigned& hi, unsigned& lo) {
    hi = packbf(x0, x1);
    float h0 = __uint_as_float(hi << 16);
    float h1 = __uint_as_float(hi & 0xffff0000u);
    lo = packbf(x0 - h0, x1 - h1);
}

__device__ __forceinline__ void mma_bf16(float* c, const unsigned* a, const unsigned* b) {
    asm volatile(
        "mma.sync.aligned.m16n8k16.row.col.f32.bf16.bf16.f32 "
        "{%0,%1,%2,%3}, {%4,%5,%6,%7}, {%8,%9}, {%0,%1,%2,%3};\n"
        : "+f"(c[0]), "+f"(c[1]), "+f"(c[2]), "+f"(c[3])
        : "r"(a[0]), "r"(a[1]), "r"(a[2]), "r"(a[3]), "r"(b[0]), "r"(b[1]));
}

// ---------------- block reduction ----------------
__device__ __forceinline__ float blockSum(float v, float* red) {
#pragma unroll
    for (int o = 16; o > 0; o >>= 1) v += __shfl_xor_sync(0xffffffffu, v, o);
    int lane = threadIdx.x & 31, w = threadIdx.x >> 5;
    if (lane == 0) red[w] = v;
    __syncthreads();
    if (w == 0) {
        float x = (lane < 16) ? red[lane] : 0.f;
#pragma unroll
        for (int o = 8; o > 0; o >>= 1) x += __shfl_xor_sync(0xffffffffu, x, o);
        if (lane == 0) red[0] = x;
    }
    __syncthreads();
    float r = red[0];
    __syncthreads();
    return r;
}

// ---------------- complex layernorm (whitening) ----------------
__global__ void cln_kernel(const float* __restrict__ xr, const float* __restrict__ xi,
                           float* __restrict__ nr, float* __restrict__ ni) {
    __shared__ float red[16];
    int row = blockIdx.x;
    int t = threadIdx.x;
    long long base = (long long)row * D_MODEL;
    float vr = xr[base + t];
    float vi = xi[base + t];
    const float invD = 1.0f / D_MODEL;
    float mr = blockSum(vr, red) * invD;
    float mi = blockSum(vi, red) * invD;
    float cr = vr - mr, ci = vi - mi;
    float Crr = blockSum(cr * cr, red) * invD + EPS_LN;
    float Cii = blockSum(ci * ci, red) * invD + EPS_LN;
    float Cri = blockSum(cr * ci, red) * invD;
    float s = sqrtf(Crr * Cii - Cri * Cri);
    float tt = sqrtf(Cii + Crr + 2.0f * s);
    float inv = 1.0f / (s * tt);
    float Rrr = (Cii + s) * inv;
    float Rii = (Crr + s) * inv;
    float Rri = -Cri * inv;
    nr[base + t] = Rrr * cr + Rri * ci;
    ni[base + t] = Rii * ci + Rri * cr;
}

// ---------------- bf16x3 split tensor-core GEMM ----------------
// C = beta*C + alpha * A @ op(B) (+bias). A:[M,Kd] row-major.
// TB ? B:[N,Kd] row-major used transposed : B:[Kd,N] row-major.
// M % 128 == 0, Kd % 16 == 0 assumed; N guarded.
template <bool TB>
__global__ void __launch_bounds__(256, 2) gemm_tc(
    const float* __restrict__ A, const float* __restrict__ B, float* __restrict__ C,
    int M, int N, int Kd, int lda, int ldb, int ldc,
    long long sA, long long sB, long long sC,
    float alpha, float beta, const float* __restrict__ bias) {
    // A: [row 0..127][kpair 0..7] xor-swizzled, pitch 8 (b32 units)
    __shared__ unsigned As[2][2][128 * 8];
    // B: TB ? [n][kpair] xor-swizzled pitch 8 : [kpair 0..7][n 0..127] pitch 136
    __shared__ unsigned Bs[2][2][TB ? (128 * 8) : (8 * 136)];

    const float* Ab = A + (long long)blockIdx.z * sA;
    const float* Bb = B + (long long)blockIdx.z * sB;
    float* Cb = C + (long long)blockIdx.z * sC;
    const int brow = blockIdx.y * 128, bcol = blockIdx.x * 128;
    const int tid = threadIdx.x;
    const int lane = tid & 31, w = tid >> 5;
    const int wr = w >> 2, wc = w & 3;        // warp tile: rows wr*64, cols wc*32
    const int gr = lane >> 2, gc = lane & 3;  // mma group row / thread-in-group
    const int kgl = gc ^ gr;                  // swizzled kpair for frag lo-k
    const int kgh = (gc + 4) ^ gr;            // swizzled kpair for frag hi-k

    float acc[4][4][4];
#pragma unroll
    for (int i = 0; i < 4; i++)
#pragma unroll
        for (int j = 0; j < 4; j++)
#pragma unroll
            for (int q = 0; q < 4; q++) acc[i][j][q] = 0.f;

    // loader indices (row-major operands): row am, k-half ak
    const int am = tid >> 1;          // 0..127
    const int ak = (tid & 1) * 8;     // float offset within KT
    const int arx = am & 7;           // xor key for this row
    const int kb = ak >> 1;           // kpair base (0 or 4)
    // loader indices (K-major B): kpair bk, col bn
    const int bk = tid >> 5;          // 0..7
    const int bn = (lane) * 4;        // 0..124

    float4 pa0, pa1, pb0, pb1;

    auto ldA = [&](int k0) {
        const float* p = &Ab[(long long)(brow + am) * lda + k0 + ak];
        pa0 = *(const float4*)p;
        pa1 = *(const float4*)(p + 4);
    };
    auto ldB = [&](int k0) {
        if (TB) {
            int gn = bcol + am;
            if (gn < N) {
                const float* p = &Bb[(long long)gn * ldb + k0 + ak];
                pb0 = *(const float4*)p;
                pb1 = *(const float4*)(p + 4);
            } else {
                pb0 = make_float4(0.f, 0.f, 0.f, 0.f);
                pb1 = pb0;
            }
        } else {
            int gn = bcol + bn;
            if (gn < N) {
                pb0 = *(const float4*)&Bb[(long long)(k0 + 2 * bk) * ldb + gn];
                pb1 = *(const float4*)&Bb[(long long)(k0 + 2 * bk + 1) * ldb + gn];
            } else {
                pb0 = make_float4(0.f, 0.f, 0.f, 0.f);
                pb1 = pb0;
            }
        }
    };
    auto stAB = [&](int buf) {
        // A: pairs (pa0.x,pa0.y),(pa0.z,pa0.w),(pa1.x,pa1.y),(pa1.z,pa1.w)
        {
            unsigned h, l;
            unsigned base = am * 8;
            split2(pa0.x, pa0.y, h, l);
            As[buf][0][base + ((kb + 0) ^ arx)] = h; As[buf][1][base + ((kb + 0) ^ arx)] = l;
            split2(pa0.z, pa0.w, h, l);
            As[buf][0][base + ((kb + 1) ^ arx)] = h; As[buf][1][base + ((kb + 1) ^ arx)] = l;
            split2(pa1.x, pa1.y, h, l);
            As[buf][0][base + ((kb + 2) ^ arx)] = h; As[buf][1][base + ((kb + 2) ^ arx)] = l;
            split2(pa1.z, pa1.w, h, l);
            As[buf][0][base + ((kb + 3) ^ arx)] = h; As[buf][1][base + ((kb + 3) ^ arx)] = l;
        }
        if (TB) {
            unsigned h, l;
            unsigned base = am * 8;
            split2(pb0.x, pb0.y, h, l);
            Bs[buf][0][base + ((kb + 0) ^ arx)] = h; Bs[buf][1][base + ((kb + 0) ^ arx)] = l;
            split2(pb0.z, pb0.w, h, l);
            Bs[buf][0][base + ((kb + 1) ^ arx)] = h; Bs[buf][1][base + ((kb + 1) ^ arx)] = l;
            split2(pb1.x, pb1.y, h, l);
            Bs[buf][0][base + ((kb + 2) ^ arx)] = h; Bs[buf][1][base + ((kb + 2) ^ arx)] = l;
            split2(pb1.z, pb1.w, h, l);
            Bs[buf][0][base + ((kb + 3) ^ arx)] = h; Bs[buf][1][base + ((kb + 3) ^ arx)] = l;
        } else {
            // pairs are along k: (pb0.j, pb1.j) -> kpair bk, col bn+j
            unsigned h, l;
            unsigned base = bk * 136 + bn;
            split2(pb0.x, pb1.x, h, l);
            Bs[buf][0][base + 0] = h; Bs[buf][1][base + 0] = l;
            split2(pb0.y, pb1.y, h, l);
            Bs[buf][0][base + 1] = h; Bs[buf][1][base + 1] = l;
            split2(pb0.z, pb1.z, h, l);
            Bs[buf][0][base + 2] = h; Bs[buf][1][base + 2] = l;
            split2(pb0.w, pb1.w, h, l);
            Bs[buf][0][base + 3] = h; Bs[buf][1][base + 3] = l;
        }
    };
    auto compute = [&](int buf) {
        unsigned bh[4][2], bl[4][2];
#pragma unroll
        for (int nt = 0; nt < 4; nt++) {
            int n = wc * 32 + nt * 8 + gr;
            if (TB) {
                bh[nt][0] = Bs[buf][0][n * 8 + kgl];
                bh[nt][1] = Bs[buf][0][n * 8 + kgh];
                bl[nt][0] = Bs[buf][1][n * 8 + kgl];
                bl[nt][1] = Bs[buf][1][n * 8 + kgh];
            } else {
                bh[nt][0] = Bs[buf][0][gc * 136 + n];
                bh[nt][1] = Bs[buf][0][(gc + 4) * 136 + n];
                bl[nt][0] = Bs[buf][1][gc * 136 + n];
                bl[nt][1] = Bs[buf][1][(gc + 4) * 136 + n];
            }
        }
#pragma unroll
        for (int mt = 0; mt < 4; mt++) {
            int m = wr * 64 + mt * 16;
            int r0 = (m + gr) * 8, r1 = (m + 8 + gr) * 8;
            unsigned ah[4], al[4];
            ah[0] = As[buf][0][r0 + kgl];
            ah[1] = As[buf][0][r1 + kgl];
            ah[2] = As[buf][0][r0 + kgh];
            ah[3] = As[buf][0][r1 + kgh];
            al[0] = As[buf][1][r0 + kgl];
            al[1] = As[buf][1][r1 + kgl];
            al[2] = As[buf][1][r0 + kgh];
            al[3] = As[buf][1][r1 + kgh];
#pragma unroll
            for (int nt = 0; nt < 4; nt++) {
                mma_bf16(acc[mt][nt], ah, bh[nt]);
                mma_bf16(acc[mt][nt], al, bh[nt]);
                mma_bf16(acc[mt][nt], ah, bl[nt]);
            }
        }
    };

    ldA(0);
    ldB(0);
    stAB(0);
    __syncthreads();
    const int ntile = Kd / KT;
    for (int t = 0; t < ntile; t++) {
        if (t + 1 < ntile) {
            ldA((t + 1) * KT);
            ldB((t + 1) * KT);
        }
        compute(t & 1);
        if (t + 1 < ntile) stAB((t + 1) & 1);
        __syncthreads();
    }

#pragma unroll
    for (int mt = 0; mt < 4; mt++) {
        int m0 = brow + wr * 64 + mt * 16 + gr;
#pragma unroll
        for (int nt = 0; nt < 4; nt++) {
            int n0 = bcol + wc * 32 + nt * 8 + gc * 2;
            if (n0 < N) {
                const float* c = acc[mt][nt];
                long long off = (long long)m0 * ldc + n0;
                float2 v;
                v.x = alpha * c[0];
                v.y = alpha * c[1];
                if (beta != 0.f) {
                    float2 o = *(const float2*)&Cb[off];
                    v.x += beta * o.x;
                    v.y += beta * o.y;
                }
                if (bias) {
                    v.x += bias[n0];
                    v.y += bias[n0 + 1];
                }
                *(float2*)&Cb[off] = v;
                off += (long long)8 * ldc;
                v.x = alpha * c[2];
                v.y = alpha * c[3];
                if (beta != 0.f) {
                    float2 o = *(const float2*)&Cb[off];
                    v.x += beta * o.x;
                    v.y += beta * o.y;
                }
                if (bias) {
                    v.x += bias[n0];
                    v.y += bias[n0 + 1];
                }
                *(float2*)&Cb[off] = v;
            }
        }
    }
}

// ---------------- split-K projection (bf16x3): P[z] = A^T @ B over token slice z ----
// A: [N_TOK, K_LR], B: [N_TOK, D_MODEL], P: [NSPLIT, K_LR, D_MODEL]
__global__ void __launch_bounds__(256, 2) proj_splitk_tc(
    const float* __restrict__ A, const float* __restrict__ B, float* __restrict__ P) {
    __shared__ unsigned As[2][2][8 * 136];
    __shared__ unsigned Bs[2][2][8 * 136];
    const int chunk = N_TOK / NSPLIT;  // 128
    const int kbeg = blockIdx.z * chunk;
    const int brow = blockIdx.y * 128, bcol = blockIdx.x * 128;
    const int tid = threadIdx.x;
    const int lane = tid & 31, w = tid >> 5;
    const int wr = w >> 2, wc = w & 3;
    const int gr = lane >> 2, gc = lane & 3;
    const int kp = tid >> 5;       // kpair 0..7
    const int an = lane * 4;       // col 0..124

    float acc[4][4][4];
#pragma unroll
    for (int i = 0; i < 4; i++)
#pragma unroll
        for (int j = 0; j < 4; j++)
#pragma unroll
            for (int q = 0; q < 4; q++) acc[i][j][q] = 0.f;

    float4 pa0, pa1, pb0, pb1;
    auto ld = [&](int k0) {
        pa0 = *(const float4*)&A[(long long)(k0 + 2 * kp) * K_LR + brow + an];
        pa1 = *(const float4*)&A[(long long)(k0 + 2 * kp + 1) * K_LR + brow + an];
        pb0 = *(const float4*)&B[(long long)(k0 + 2 * kp) * D_MODEL + bcol + an];
        pb1 = *(const float4*)&B[(long long)(k0 + 2 * kp + 1) * D_MODEL + bcol + an];
    };
    auto st = [&](int buf) {
        unsigned h, l;
        unsigned base = kp * 136 + an;
        split2(pa0.x, pa1.x, h, l); As[buf][0][base + 0] = h; As[buf][1][base + 0] = l;
        split2(pa0.y, pa1.y, h, l); As[buf][0][base + 1] = h; As[buf][1][base + 1] = l;
        split2(pa0.z, pa1.z, h, l); As[buf][0][base + 2] = h; As[buf][1][base + 2] = l;
        split2(pa0.w, pa1.w, h, l); As[buf][0][base + 3] = h; As[buf][1][base + 3] = l;
        split2(pb0.x, pb1.x, h, l); Bs[buf][0][base + 0] = h; Bs[buf][1][base + 0] = l;
        split2(pb0.y, pb1.y, h, l); Bs[buf][0][base + 1] = h; Bs[buf][1][base + 1] = l;
        split2(pb0.z, pb1.z, h, l); Bs[buf][0][base + 2] = h; Bs[buf][1][base + 2] = l;
        split2(pb0.w, pb1.w, h, l); Bs[buf][0][base + 3] = h; Bs[buf][1][base + 3] = l;
    };
    auto compute = [&](int buf) {
        unsigned bh[4][2], bl[4][2];
#pragma unroll
        for (int nt = 0; nt < 4; nt++) {
            int n = wc * 32 + nt * 8 + gr;
            bh[nt][0] = Bs[buf][0][gc * 136 + n];
            bh[nt][1] = Bs[buf][0][(gc + 4) * 136 + n];
            bl[nt][0] = Bs[buf][1][gc * 136 + n];
            bl[nt][1] = Bs[buf][1][(gc + 4) * 136 + n];
        }
#pragma unroll
        for (int mt = 0; mt < 4; mt++) {
            int m = wr * 64 + mt * 16;
            unsigned ah[4], al[4];
            ah[0] = As[buf][0][gc * 136 + m + gr];
            ah[1] = As[buf][0][gc * 136 + m + 8 + gr];
            ah[2] = As[buf][0][(gc + 4) * 136 + m + gr];
            ah[3] = As[buf][0][(gc + 4) * 136 + m + 8 + gr];
            al[0] = As[buf][1][gc * 136 + m + gr];
            al[1] = As[buf][1][gc * 136 + m + 8 + gr];
            al[2] = As[buf][1][(gc + 4) * 136 + m + gr];
            al[3] = As[buf][1][(gc + 4) * 136 + m + 8 + gr];
#pragma unroll
            for (int nt = 0; nt < 4; nt++) {
                mma_bf16(acc[mt][nt], ah, bh[nt]);
                mma_bf16(acc[mt][nt], al, bh[nt]);
                mma_bf16(acc[mt][nt], ah, bl[nt]);
            }
        }
    };

    ld(kbeg);
    st(0);
    __syncthreads();
    const int ntile = chunk / KT;  // 8
    for (int t = 0; t < ntile; t++) {
        if (t + 1 < ntile) ld(kbeg + (t + 1) * KT);
        compute(t & 1);
        if (t + 1 < ntile) st((t + 1) & 1);
        __syncthreads();
    }

    float* Pz = P + (long long)blockIdx.z * K_LR * D_MODEL;
#pragma unroll
    for (int mt = 0; mt < 4; mt++) {
        int m0 = brow + wr * 64 + mt * 16 + gr;
#pragma unroll
        for (int nt = 0; nt < 4; nt++) {
            int n0 = bcol + wc * 32 + nt * 8 + gc * 2;
            const float* c = acc[mt][nt];
            *(float2*)&Pz[(long long)m0 * D_MODEL + n0] = make_float2(c[0], c[1]);
            *(float2*)&Pz[(long long)(m0 + 8) * D_MODEL + n0] = make_float2(c[2], c[3]);
        }
    }
}

__global__ void proj_reduce_kernel(const float* __restrict__ P,
                                   float* __restrict__ kpr, float* __restrict__ kpi,
                                   float* __restrict__ vpr, float* __restrict__ vpi) {
    const int n = K_LR * D_MODEL;
    int i = blockIdx.x * blockDim.x + threadIdx.x;
    if (i >= n) return;
    float* outs[4] = {kpr, kpi, vpr, vpi};
#pragma unroll
    for (int p = 0; p < 4; p++) {
        const float* base = P + (long long)p * NSPLIT * n + i;
        float s = 0.f;
#pragma unroll
        for (int z = 0; z < NSPLIT; z++) s += base[(long long)z * n];
        outs[p][i] = s;
    }
}

__global__ void relu2_kernel(float* __restrict__ a, float* __restrict__ b, int n) {
    int i = blockIdx.x * blockDim.x + threadIdx.x;
    int stride = gridDim.x * blockDim.x;
    for (; i < n; i += stride) {
        a[i] = fmaxf(a[i], 0.f);
        b[i] = fmaxf(b[i], 0.f);
    }
}

// ---------------- host launcher ----------------
static inline void gemmL(const float* A, const float* B, float* C,
                         int M, int N, int Kd, int lda, int ldb, int ldc,
                         long long sA, long long sB, long long sC, int batch,
                         float alpha, float beta, const float* bias, bool tb) {
    dim3 grid((N + 127) / 128, (M + 127) / 128, batch);
    if (tb)
        gemm_tc<true><<<grid, 256>>>(A, B, C, M, N, Kd, lda, ldb, ldc, sA, sB, sC, alpha, beta, bias);
    else
        gemm_tc<false><<<grid, 256>>>(A, B, C, M, N, Kd, lda, ldb, ldc, sA, sB, sC, alpha, beta, bias);
}

extern "C" void kernel_launch(void* const* d_in, const int* in_sizes, int n_in,
                              void* d_out, int out_size) {
    const float* x_real = (const float*)d_in[0];
    const float* x_imag = (const float*)d_in[1];
    const float* Wq = (const float*)d_in[2];
    const float* bq = (const float*)d_in[3];
    const float* Wk = (const float*)d_in[4];
    const float* bk = (const float*)d_in[5];
    const float* Wv = (const float*)d_in[6];
    const float* bv = (const float*)d_in[7];
    const float* pk = (const float*)d_in[8];
    const float* pv = (const float*)d_in[9];
    const float* Wout = (const float*)d_in[10];
    const float* bout = (const float*)d_in[11];
    const float* W1r = (const float*)d_in[12];
    const float* W1i = (const float*)d_in[13];
    const float* b1r = (const float*)d_in[14];
    const float* b1i = (const float*)d_in[15];
    const float* W2r = (const float*)d_in[16];
    const float* W2i = (const float*)d_in[17];
    const float* b2r = (const float*)d_in[18];
    const float* b2i = (const float*)d_in[19];

    float* xr = (float*)d_out;
    float* xi = xr + (size_t)N_TOK * D_MODEL;

    float *NR, *NI, *QR, *QI, *KR, *KI, *VR, *VI;
    float *KPR, *KPI, *VPR, *VPI, *DR, *DI, *ORr, *OIr, *HR, *HI, *PSUM;
    cudaGetSymbolAddress((void**)&NR, g_NR);
    cudaGetSymbolAddress((void**)&NI, g_NI);
    cudaGetSymbolAddress((void**)&QR, g_QR);
    cudaGetSymbolAddress((void**)&QI, g_QI);
    cudaGetSymbolAddress((void**)&KR, g_KR);
    cudaGetSymbolAddress((void**)&KI, g_KI);
    cudaGetSymbolAddress((void**)&VR, g_VR);
    cudaGetSymbolAddress((void**)&VI, g_VI);
    cudaGetSymbolAddress((void**)&KPR, g_KPR);
    cudaGetSymbolAddress((void**)&KPI, g_KPI);
    cudaGetSymbolAddress((void**)&VPR, g_VPR);
    cudaGetSymbolAddress((void**)&VPI, g_VPI);
    cudaGetSymbolAddress((void**)&DR, g_DR);
    cudaGetSymbolAddress((void**)&DI, g_DI);
    cudaGetSymbolAddress((void**)&ORr, g_OR);
    cudaGetSymbolAddress((void**)&OIr, g_OI);
    cudaGetSymbolAddress((void**)&HR, g_HR);
    cudaGetSymbolAddress((void**)&HI, g_HI);
    cudaGetSymbolAddress((void**)&PSUM, g_PSUM);

    const size_t ND_BYTES = (size_t)N_TOK * D_MODEL * sizeof(float);
    cudaMemcpyAsync(xr, x_real, ND_BYTES, cudaMemcpyDeviceToDevice, 0);
    cudaMemcpyAsync(xi, x_imag, ND_BYTES, cudaMemcpyDeviceToDevice, 0);

    const long long NK = (long long)N_TOK * K_LR;
    const long long PSZ = (long long)NSPLIT * K_LR * D_MODEL;

    for (int d = 0; d < 2; d++) {
        const float* Wq_d = Wq + (size_t)d * D_MODEL * D_MODEL;
        const float* bq_d = bq + (size_t)d * D_MODEL;
        const float* Wk_d = Wk + (size_t)d * D_MODEL * D_MODEL;
        const float* bk_d = bk + (size_t)d * D_MODEL;
        const float* Wv_d = Wv + (size_t)d * D_MODEL * D_MODEL;
        const float* bv_d = bv + (size_t)d * D_MODEL;
        const float* pk_d = pk + (size_t)d * N_TOK * K_LR;
        const float* pv_d = pv + (size_t)d * N_TOK * K_LR;
        const float* Wo_d = Wout + (size_t)d * D_MODEL * D_MODEL;
        const float* bo_d = bout + (size_t)d * D_MODEL;
        const float* W1r_d = W1r + (size_t)d * D_MODEL * D_FF;
        const float* W1i_d = W1i + (size_t)d * D_MODEL * D_FF;
        const float* b1r_d = b1r + (size_t)d * D_FF;
        const float* b1i_d = b1i + (size_t)d * D_FF;
        const float* W2r_d = W2r + (size_t)d * D_FF * D_MODEL;
        const float* W2i_d = W2i + (size_t)d * D_FF * D_MODEL;
        const float* b2r_d = b2r + (size_t)d * D_MODEL;
        const float* b2i_d = b2i + (size_t)d * D_MODEL;

        // ---- LN1
        cln_kernel<<<N_TOK, 512>>>(xr, xi, NR, NI);

        // ---- QKV
        gemmL(NR, Wq_d, QR, N_TOK, D_MODEL, D_MODEL, D_MODEL, D_MODEL, D_MODEL, 0, 0, 0, 1, 1.f, 0.f, bq_d, false);
        gemmL(NI, Wq_d, QI, N_TOK, D_MODEL, D_MODEL, D_MODEL, D_MODEL, D_MODEL, 0, 0, 0, 1, 1.f, 0.f, bq_d, false);
        gemmL(NR, Wk_d, KR, N_TOK, D_MODEL, D_MODEL, D_MODEL, D_MODEL, D_MODEL, 0, 0, 0, 1, 1.f, 0.f, bk_d, false);
        gemmL(NI, Wk_d, KI, N_TOK, D_MODEL, D_MODEL, D_MODEL, D_MODEL, D_MODEL, 0, 0, 0, 1, 1.f, 0.f, bk_d, false);
        gemmL(NR, Wv_d, VR, N_TOK, D_MODEL, D_MODEL, D_MODEL, D_MODEL, D_MODEL, 0, 0, 0, 1, 1.f, 0.f, bv_d, false);
        gemmL(NI, Wv_d, VI, N_TOK, D_MODEL, D_MODEL, D_MODEL, D_MODEL, D_MODEL, 0, 0, 0, 1, 1.f, 0.f, bv_d, false);

        // ---- low-rank projections (split-K, deterministic reduce)
        {
            dim3 g(D_MODEL / 128, K_LR / 128, NSPLIT);
            proj_splitk_tc<<<g, 256>>>(pk_d, KR, PSUM + 0 * PSZ);
            proj_splitk_tc<<<g, 256>>>(pk_d, KI, PSUM + 1 * PSZ);
            proj_splitk_tc<<<g, 256>>>(pv_d, VR, PSUM + 2 * PSZ);
            proj_splitk_tc<<<g, 256>>>(pv_d, VI, PSUM + 3 * PSZ);
            proj_reduce_kernel<<<(K_LR * D_MODEL + 255) / 256, 256>>>(PSUM, KPR, KPI, VPR, VPI);
        }

        // ---- complex dots per head
        gemmL(QR, KPR, DR, N_TOK, K_LR, DHEAD, D_MODEL, D_MODEL, K_LR, DHEAD, DHEAD, NK, H_HEADS, ATTN_SCALE, 0.f, nullptr, true);
        gemmL(QI, KPI, DR, N_TOK, K_LR, DHEAD, D_MODEL, D_MODEL, K_LR, DHEAD, DHEAD, NK, H_HEADS, -ATTN_SCALE, 1.f, nullptr, true);
        gemmL(QR, KPI, DI, N_TOK, K_LR, DHEAD, D_MODEL, D_MODEL, K_LR, DHEAD, DHEAD, NK, H_HEADS, ATTN_SCALE, 0.f, nullptr, true);
        gemmL(QI, KPR, DI, N_TOK, K_LR, DHEAD, D_MODEL, D_MODEL, K_LR, DHEAD, DHEAD, NK, H_HEADS, ATTN_SCALE, 1.f, nullptr, true);

        // ---- attn out per head
        gemmL(DR, VPR, ORr, N_TOK, DHEAD, K_LR, K_LR, D_MODEL, D_MODEL, NK, DHEAD, DHEAD, H_HEADS, 1.f, 0.f, nullptr, false);
        gemmL(DI, VPI, ORr, N_TOK, DHEAD, K_LR, K_LR, D_MODEL, D_MODEL, NK, DHEAD, DHEAD, H_HEADS, -1.f, 1.f, nullptr, false);
        gemmL(DR, VPI, OIr, N_TOK, DHEAD, K_LR, K_LR, D_MODEL, D_MODEL, NK, DHEAD, DHEAD, H_HEADS, 1.f, 0.f, nullptr, false);
        gemmL(DI, VPR, OIr, N_TOK, DHEAD, K_LR, K_LR, D_MODEL, D_MODEL, NK, DHEAD, DHEAD, H_HEADS, 1.f, 1.f, nullptr, false);

        // ---- output projection + residual
        gemmL(ORr, Wo_d, xr, N_TOK, D_MODEL, D_MODEL, D_MODEL, D_MODEL, D_MODEL, 0, 0, 0, 1, 1.f, 1.f, bo_d, false);
        gemmL(OIr, Wo_d, xi, N_TOK, D_MODEL, D_MODEL, D_MODEL, D_MODEL, D_MODEL, 0, 0, 0, 1, 1.f, 1.f, bo_d, false);

        // ---- LN2
        cln_kernel<<<N_TOK, 512>>>(xr, xi, NR, NI);

        // ---- complex FFN
        gemmL(NR, W1r_d, HR, N_TOK, D_FF, D_MODEL, D_MODEL, D_FF, D_FF, 0, 0, 0, 1, 1.f, 0.f, b1r_d, false);
        gemmL(NI, W1i_d, HR, N_TOK, D_FF, D_MODEL, D_MODEL, D_FF, D_FF, 0, 0, 0, 1, -1.f, 1.f, nullptr, false);
        gemmL(NR, W1i_d, HI, N_TOK, D_FF, D_MODEL, D_MODEL, D_FF, D_FF, 0, 0, 0, 1, 1.f, 0.f, b1i_d, false);
        gemmL(NI, W1r_d, HI, N_TOK, D_FF, D_MODEL, D_MODEL, D_FF, D_FF, 0, 0, 0, 1, 1.f, 1.f, nullptr, false);
        relu2_kernel<<<4096, 256>>>(HR, HI, N_TOK * D_FF);
        gemmL(HR, W2r_d, xr, N_TOK, D_MODEL, D_FF, D_FF, D_MODEL, D_MODEL, 0, 0, 0, 1, 1.f, 1.f, b2r_d, false);
        gemmL(HI, W2i_d, xr, N_TOK, D_MODEL, D_FF, D_FF, D_MODEL, D_MODEL, 0, 0, 0, 1, -1.f, 1.f, nullptr, false);
        gemmL(HR, W2i_d, xi, N_TOK, D_MODEL, D_FF, D_FF, D_MODEL, D_MODEL, 0, 0, 0, 1, 1.f, 1.f, b2i_d, false);
        gemmL(HI, W2r_d, xi, N_TOK, D_MODEL, D_FF, D_FF, D_MODEL, D_MODEL, 0, 0, 0, 1, 1.f, 1.f, nullptr, false);
    }
}

// round 4
// speedup vs baseline: 2.6995x; 1.1988x over previous
#include <cuda_runtime.h>
#include <cstdint>

#define N_TOK 4096
#define D_MODEL 512
#define K_LR 256
#define H_HEADS 8
#define DHEAD 64
#define D_FF 2048
#define EPS_LN 1e-5f
#define ATTN_SCALE 0.125f
#define NSPLIT 32
#define KT 16

#define ND ((long long)N_TOK * D_MODEL)
#define KD ((long long)K_LR * D_MODEL)
#define NK ((long long)N_TOK * K_LR)
#define HNK ((long long)H_HEADS * N_TOK * K_LR)
#define NFF ((long long)N_TOK * D_FF)

// ---------------- scratch (device globals: allocation-free) ----------------
__device__ float g_N[2 * N_TOK * D_MODEL];                      // NR, NI
__device__ float g_QKV[6 * N_TOK * D_MODEL];                    // QR,QI,KR,KI,VR,VI
__device__ float g_P4[4 * K_LR * D_MODEL];                      // KPR,KPI,VPR,VPI
__device__ float g_D[(size_t)2 * H_HEADS * N_TOK * K_LR];       // DR, DI
__device__ float g_O[2 * N_TOK * D_MODEL];                      // OR, OI
__device__ float g_H[(size_t)2 * N_TOK * D_FF];                 // HR, HI
__device__ float g_PSUM[(size_t)4 * NSPLIT * K_LR * D_MODEL];

// ---------------- bf16 split helpers ----------------
__device__ __forceinline__ unsigned packbf(float x0, float x1) {
    unsigned r;
    asm("cvt.rn.bf16x2.f32 %0, %1, %2;" : "=r"(r) : "f"(x1), "f"(x0));
    return r;
}
__device__ __forceinline__ void split2(float x0, float x1, unsigned& hi, unsigned& lo) {
    hi = packbf(x0, x1);
    float h0 = __uint_as_float(hi << 16);
    float h1 = __uint_as_float(hi & 0xffff0000u);
    lo = packbf(x0 - h0, x1 - h1);
}
__device__ __forceinline__ void mma_bf16(float* c, const unsigned* a, const unsigned* b) {
    asm volatile(
        "mma.sync.aligned.m16n8k16.row.col.f32.bf16.bf16.f32 "
        "{%0,%1,%2,%3}, {%4,%5,%6,%7}, {%8,%9}, {%0,%1,%2,%3};\n"
        : "+f"(c[0]), "+f"(c[1]), "+f"(c[2]), "+f"(c[3])
        : "r"(a[0]), "r"(a[1]), "r"(a[2]), "r"(a[3]), "r"(b[0]), "r"(b[1]));
}

// ---------------- block reduction ----------------
__device__ __forceinline__ float blockSum(float v, float* red) {
#pragma unroll
    for (int o = 16; o > 0; o >>= 1) v += __shfl_xor_sync(0xffffffffu, v, o);
    int lane = threadIdx.x & 31, w = threadIdx.x >> 5;
    if (lane == 0) red[w] = v;
    __syncthreads();
    if (w == 0) {
        float x = (lane < 16) ? red[lane] : 0.f;
#pragma unroll
        for (int o = 8; o > 0; o >>= 1) x += __shfl_xor_sync(0xffffffffu, x, o);
        if (lane == 0) red[0] = x;
    }
    __syncthreads();
    float r = red[0];
    __syncthreads();
    return r;
}

// ---------------- complex layernorm (whitening) ----------------
__global__ void cln_kernel(const float* __restrict__ xr, const float* __restrict__ xi,
                           float* __restrict__ nr, float* __restrict__ ni) {
    __shared__ float red[16];
    int row = blockIdx.x;
    int t = threadIdx.x;
    long long base = (long long)row * D_MODEL;
    float vr = xr[base + t];
    float vi = xi[base + t];
    const float invD = 1.0f / D_MODEL;
    float mr = blockSum(vr, red) * invD;
    float mi = blockSum(vi, red) * invD;
    float cr = vr - mr, ci = vi - mi;
    float Crr = blockSum(cr * cr, red) * invD + EPS_LN;
    float Cii = blockSum(ci * ci, red) * invD + EPS_LN;
    float Cri = blockSum(cr * ci, red) * invD;
    float s = sqrtf(Crr * Cii - Cri * Cri);
    float tt = sqrtf(Cii + Crr + 2.0f * s);
    float inv = 1.0f / (s * tt);
    float Rrr = (Cii + s) * inv;
    float Rii = (Crr + s) * inv;
    float Rri = -Cri * inv;
    nr[base + t] = Rrr * cr + Rri * ci;
    ni[base + t] = Rii * ci + Rri * cr;
}

// ---------------- bf16x3 complex/chained tensor-core GEMM ----------------
// nzc==1: C[z] = beta*C + alpha*A1[z]@op(B1[z]) + bias1      (A2 must be null)
// nzc==2: z=(bz,part). part0: C = beta*C + alpha*(A1@B1 - A2@B2) + bias1
//                      part1: C = beta*C + alpha*(A1@B2 + A2@B1) + bias2
// A:[M,Kd] row-major. TB ? B:[N,Kd] used transposed : B:[Kd,N].
// M%128==0, Kd%16==0; N guarded.
template <bool TB>
__global__ void __launch_bounds__(256, 2) gemm_cx(
    const float* __restrict__ A1, const float* __restrict__ A2,
    const float* __restrict__ B1, const float* __restrict__ B2,
    float* __restrict__ C, const float* __restrict__ bias1, const float* __restrict__ bias2,
    int M, int N, int Kd, int lda, int ldb, int ldc,
    long long sA, long long sB, long long sC, long long sCp,
    float alpha, float beta, int nzc) {
    __shared__ unsigned As[2][2][128 * 8];
    __shared__ unsigned Bs[2][2][TB ? (128 * 8) : (8 * 136)];

    const int z = blockIdx.z;
    const int part = (nzc == 2) ? (z & 1) : 0;
    const int bz = (nzc == 2) ? (z >> 1) : z;

    const float* Au0 = A1 + (long long)bz * sA;
    const float* Au1 = A2 ? A2 + (long long)bz * sA : nullptr;
    const float* Bu0;
    const float* Bu1 = nullptr;
    float s2 = 1.f;
    const float* biasz;
    if (part == 0) {
        Bu0 = B1 + (long long)bz * sB;
        if (A2) Bu1 = B2 + (long long)bz * sB;
        s2 = -1.f;
        biasz = bias1;
    } else {
        Bu0 = B2 + (long long)bz * sB;
        Bu1 = B1 + (long long)bz * sB;
        s2 = 1.f;
        biasz = bias2;
    }
    float* Cb = C + (long long)bz * sC + (long long)part * sCp;

    const int brow = blockIdx.y * 128, bcol = blockIdx.x * 128;
    const int tid = threadIdx.x;
    const int lane = tid & 31, w = tid >> 5;
    const int wr = w >> 2, wc = w & 3;
    const int gr = lane >> 2, gc = lane & 3;
    const int kgl = gc ^ gr;
    const int kgh = (gc + 4) ^ gr;

    float acc[4][4][4];
#pragma unroll
    for (int i = 0; i < 4; i++)
#pragma unroll
        for (int j = 0; j < 4; j++)
#pragma unroll
            for (int q = 0; q < 4; q++) acc[i][j][q] = 0.f;

    const int am = tid >> 1;
    const int ak = (tid & 1) * 8;
    const int arx = am & 7;
    const int kb = ak >> 1;
    const int bk = tid >> 5;
    const int bn = lane * 4;

    float4 pa0, pa1, pb0, pb1;
    float psg = 1.f;

    const int ntile1 = Kd / KT;
    const int ntot = (A2 ? 2 : 1) * ntile1;

    auto ld = [&](int t) {
        int ch = (t >= ntile1);
        const float* Ab = ch ? Au1 : Au0;
        const float* Bb = ch ? Bu1 : Bu0;
        psg = ch ? s2 : 1.f;
        int k0 = (ch ? t - ntile1 : t) * KT;
        {
            const float* p = &Ab[(long long)(brow + am) * lda + k0 + ak];
            pa0 = *(const float4*)p;
            pa1 = *(const float4*)(p + 4);
        }
        if (TB) {
            int gn = bcol + am;
            if (gn < N) {
                const float* p = &Bb[(long long)gn * ldb + k0 + ak];
                pb0 = *(const float4*)p;
                pb1 = *(const float4*)(p + 4);
            } else {
                pb0 = make_float4(0.f, 0.f, 0.f, 0.f);
                pb1 = pb0;
            }
        } else {
            int gn = bcol + bn;
            if (gn < N) {
                pb0 = *(const float4*)&Bb[(long long)(k0 + 2 * bk) * ldb + gn];
                pb1 = *(const float4*)&Bb[(long long)(k0 + 2 * bk + 1) * ldb + gn];
            } else {
                pb0 = make_float4(0.f, 0.f, 0.f, 0.f);
                pb1 = pb0;
            }
        }
    };
    auto stAB = [&](int buf) {
        {
            unsigned h, l;
            unsigned base = am * 8;
            split2(pa0.x, pa0.y, h, l);
            As[buf][0][base + ((kb + 0) ^ arx)] = h; As[buf][1][base + ((kb + 0) ^ arx)] = l;
            split2(pa0.z, pa0.w, h, l);
            As[buf][0][base + ((kb + 1) ^ arx)] = h; As[buf][1][base + ((kb + 1) ^ arx)] = l;
            split2(pa1.x, pa1.y, h, l);
            As[buf][0][base + ((kb + 2) ^ arx)] = h; As[buf][1][base + ((kb + 2) ^ arx)] = l;
            split2(pa1.z, pa1.w, h, l);
            As[buf][0][base + ((kb + 3) ^ arx)] = h; As[buf][1][base + ((kb + 3) ^ arx)] = l;
        }
        float sg = psg;
        if (TB) {
            unsigned h, l;
            unsigned base = am * 8;
            split2(sg * pb0.x, sg * pb0.y, h, l);
            Bs[buf][0][base + ((kb + 0) ^ arx)] = h; Bs[buf][1][base + ((kb + 0) ^ arx)] = l;
            split2(sg * pb0.z, sg * pb0.w, h, l);
            Bs[buf][0][base + ((kb + 1) ^ arx)] = h; Bs[buf][1][base + ((kb + 1) ^ arx)] = l;
            split2(sg * pb1.x, sg * pb1.y, h, l);
            Bs[buf][0][base + ((kb + 2) ^ arx)] = h; Bs[buf][1][base + ((kb + 2) ^ arx)] = l;
            split2(sg * pb1.z, sg * pb1.w, h, l);
            Bs[buf][0][base + ((kb + 3) ^ arx)] = h; Bs[buf][1][base + ((kb + 3) ^ arx)] = l;
        } else {
            unsigned h, l;
            unsigned base = bk * 136 + bn;
            split2(sg * pb0.x, sg * pb1.x, h, l);
            Bs[buf][0][base + 0] = h; Bs[buf][1][base + 0] = l;
            split2(sg * pb0.y, sg * pb1.y, h, l);
            Bs[buf][0][base + 1] = h; Bs[buf][1][base + 1] = l;
            split2(sg * pb0.z, sg * pb1.z, h, l);
            Bs[buf][0][base + 2] = h; Bs[buf][1][base + 2] = l;
            split2(sg * pb0.w, sg * pb1.w, h, l);
            Bs[buf][0][base + 3] = h; Bs[buf][1][base + 3] = l;
        }
    };
    auto compute = [&](int buf) {
        unsigned bh[4][2], bl[4][2];
#pragma unroll
        for (int nt = 0; nt < 4; nt++) {
            int n = wc * 32 + nt * 8 + gr;
            if (TB) {
                bh[nt][0] = Bs[buf][0][n * 8 + kgl];
                bh[nt][1] = Bs[buf][0][n * 8 + kgh];
                bl[nt][0] = Bs[buf][1][n * 8 + kgl];
                bl[nt][1] = Bs[buf][1][n * 8 + kgh];
            } else {
                bh[nt][0] = Bs[buf][0][gc * 136 + n];
                bh[nt][1] = Bs[buf][0][(gc + 4) * 136 + n];
                bl[nt][0] = Bs[buf][1][gc * 136 + n];
                bl[nt][1] = Bs[buf][1][(gc + 4) * 136 + n];
            }
        }
#pragma unroll
        for (int mt = 0; mt < 4; mt++) {
            int m = wr * 64 + mt * 16;
            int r0 = (m + gr) * 8, r1 = (m + 8 + gr) * 8;
            unsigned ah[4], al[4];
            ah[0] = As[buf][0][r0 + kgl];
            ah[1] = As[buf][0][r1 + kgl];
            ah[2] = As[buf][0][r0 + kgh];
            ah[3] = As[buf][0][r1 + kgh];
            al[0] = As[buf][1][r0 + kgl];
            al[1] = As[buf][1][r1 + kgl];
            al[2] = As[buf][1][r0 + kgh];
            al[3] = As[buf][1][r1 + kgh];
#pragma unroll
            for (int nt = 0; nt < 4; nt++) {
                mma_bf16(acc[mt][nt], ah, bh[nt]);
                mma_bf16(acc[mt][nt], al, bh[nt]);
                mma_bf16(acc[mt][nt], ah, bl[nt]);
            }
        }
    };

    ld(0);
    stAB(0);
    __syncthreads();
    for (int t = 0; t < ntot; t++) {
        if (t + 1 < ntot) ld(t + 1);
        compute(t & 1);
        if (t + 1 < ntot) stAB((t + 1) & 1);
        __syncthreads();
    }

#pragma unroll
    for (int mt = 0; mt < 4; mt++) {
        int m0 = brow + wr * 64 + mt * 16 + gr;
#pragma unroll
        for (int nt = 0; nt < 4; nt++) {
            int n0 = bcol + wc * 32 + nt * 8 + gc * 2;
            if (n0 < N) {
                const float* c = acc[mt][nt];
                long long off = (long long)m0 * ldc + n0;
                float2 v;
                v.x = alpha * c[0];
                v.y = alpha * c[1];
                if (beta != 0.f) {
                    float2 o = *(const float2*)&Cb[off];
                    v.x += beta * o.x;
                    v.y += beta * o.y;
                }
                if (biasz) {
                    v.x += biasz[n0];
                    v.y += biasz[n0 + 1];
                }
                *(float2*)&Cb[off] = v;
                off += (long long)8 * ldc;
                v.x = alpha * c[2];
                v.y = alpha * c[3];
                if (beta != 0.f) {
                    float2 o = *(const float2*)&Cb[off];
                    v.x += beta * o.x;
                    v.y += beta * o.y;
                }
                if (biasz) {
                    v.x += biasz[n0];
                    v.y += biasz[n0 + 1];
                }
                *(float2*)&Cb[off] = v;
            }
        }
    }
}

// ---------------- split-K projection (bf16x3): all 4 proj GEMMs in one launch ----
// z = p*NSPLIT + s. p selects (pk,KR),(pk,KI),(pv,VR),(pv,VI); s = token slice.
// PSUM[z] = A_p[slice s]^T @ B_p[slice s]
__global__ void __launch_bounds__(256, 2) proj_splitk_tc(
    const float* __restrict__ pk, const float* __restrict__ pv,
    const float* __restrict__ KV,  // = &g_QKV[2*ND] : KR,KI,VR,VI contiguous
    float* __restrict__ P) {
    __shared__ unsigned As[2][2][8 * 136];
    __shared__ unsigned Bs[2][2][8 * 136];
    const int z = blockIdx.z;
    const int p = z >> 5;
    const int s = z & 31;
    const float* A = (p < 2) ? pk : pv;
    const float* B = KV + (long long)p * ND;
    const int chunk = N_TOK / NSPLIT;
    const int kbeg = s * chunk;
    const int brow = blockIdx.y * 128, bcol = blockIdx.x * 128;
    const int tid = threadIdx.x;
    const int lane = tid & 31, w = tid >> 5;
    const int wr = w >> 2, wc = w & 3;
    const int gr = lane >> 2, gc = lane & 3;
    const int kp = tid >> 5;
    const int an = lane * 4;

    float acc[4][4][4];
#pragma unroll
    for (int i = 0; i < 4; i++)
#pragma unroll
        for (int j = 0; j < 4; j++)
#pragma unroll
            for (int q = 0; q < 4; q++) acc[i][j][q] = 0.f;

    float4 pa0, pa1, pb0, pb1;
    auto ld = [&](int k0) {
        pa0 = *(const float4*)&A[(long long)(k0 + 2 * kp) * K_LR + brow + an];
        pa1 = *(const float4*)&A[(long long)(k0 + 2 * kp + 1) * K_LR + brow + an];
        pb0 = *(const float4*)&B[(long long)(k0 + 2 * kp) * D_MODEL + bcol + an];
        pb1 = *(const float4*)&B[(long long)(k0 + 2 * kp + 1) * D_MODEL + bcol + an];
    };
    auto st = [&](int buf) {
        unsigned h, l;
        unsigned base = kp * 136 + an;
        split2(pa0.x, pa1.x, h, l); As[buf][0][base + 0] = h; As[buf][1][base + 0] = l;
        split2(pa0.y, pa1.y, h, l); As[buf][0][base + 1] = h; As[buf][1][base + 1] = l;
        split2(pa0.z, pa1.z, h, l); As[buf][0][base + 2] = h; As[buf][1][base + 2] = l;
        split2(pa0.w, pa1.w, h, l); As[buf][0][base + 3] = h; As[buf][1][base + 3] = l;
        split2(pb0.x, pb1.x, h, l); Bs[buf][0][base + 0] = h; Bs[buf][1][base + 0] = l;
        split2(pb0.y, pb1.y, h, l); Bs[buf][0][base + 1] = h; Bs[buf][1][base + 1] = l;
        split2(pb0.z, pb1.z, h, l); Bs[buf][0][base + 2] = h; Bs[buf][1][base + 2] = l;
        split2(pb0.w, pb1.w, h, l); Bs[buf][0][base + 3] = h; Bs[buf][1][base + 3] = l;
    };
    auto compute = [&](int buf) {
        unsigned bh[4][2], bl[4][2];
#pragma unroll
        for (int nt = 0; nt < 4; nt++) {
            int n = wc * 32 + nt * 8 + gr;
            bh[nt][0] = Bs[buf][0][gc * 136 + n];
            bh[nt][1] = Bs[buf][0][(gc + 4) * 136 + n];
            bl[nt][0] = Bs[buf][1][gc * 136 + n];
            bl[nt][1] = Bs[buf][1][(gc + 4) * 136 + n];
        }
#pragma unroll
        for (int mt = 0; mt < 4; mt++) {
            int m = wr * 64 + mt * 16;
            unsigned ah[4], al[4];
            ah[0] = As[buf][0][gc * 136 + m + gr];
            ah[1] = As[buf][0][gc * 136 + m + 8 + gr];
            ah[2] = As[buf][0][(gc + 4) * 136 + m + gr];
            ah[3] = As[buf][0][(gc + 4) * 136 + m + 8 + gr];
            al[0] = As[buf][1][gc * 136 + m + gr];
            al[1] = As[buf][1][gc * 136 + m + 8 + gr];
            al[2] = As[buf][1][(gc + 4) * 136 + m + gr];
            al[3] = As[buf][1][(gc + 4) * 136 + m + 8 + gr];
#pragma unroll
            for (int nt = 0; nt < 4; nt++) {
                mma_bf16(acc[mt][nt], ah, bh[nt]);
                mma_bf16(acc[mt][nt], al, bh[nt]);
                mma_bf16(acc[mt][nt], ah, bl[nt]);
            }
        }
    };

    ld(kbeg);
    st(0);
    __syncthreads();
    const int ntile = chunk / KT;
    for (int t = 0; t < ntile; t++) {
        if (t + 1 < ntile) ld(kbeg + (t + 1) * KT);
        compute(t & 1);
        if (t + 1 < ntile) st((t + 1) & 1);
        __syncthreads();
    }

    float* Pz = P + (long long)z * KD;
#pragma unroll
    for (int mt = 0; mt < 4; mt++) {
        int m0 = brow + wr * 64 + mt * 16 + gr;
#pragma unroll
        for (int nt = 0; nt < 4; nt++) {
            int n0 = bcol + wc * 32 + nt * 8 + gc * 2;
            const float* c = acc[mt][nt];
            *(float2*)&Pz[(long long)m0 * D_MODEL + n0] = make_float2(c[0], c[1]);
            *(float2*)&Pz[(long long)(m0 + 8) * D_MODEL + n0] = make_float2(c[2], c[3]);
        }
    }
}

__global__ void proj_reduce_kernel(const float* __restrict__ P, float* __restrict__ P4) {
    const int n = K_LR * D_MODEL;
    int i = blockIdx.x * blockDim.x + threadIdx.x;
    if (i >= n) return;
#pragma unroll
    for (int p = 0; p < 4; p++) {
        const float* base = P + (long long)p * NSPLIT * n + i;
        float s = 0.f;
#pragma unroll
        for (int zz = 0; zz < NSPLIT; zz++) s += base[(long long)zz * n];
        P4[(long long)p * n + i] = s;
    }
}

__global__ void relu_kernel(float* __restrict__ a, long long n) {
    long long i = (long long)blockIdx.x * blockDim.x + threadIdx.x;
    long long stride = (long long)gridDim.x * blockDim.x;
    for (; i < n; i += stride) a[i] = fmaxf(a[i], 0.f);
}

// ---------------- host launcher ----------------
static inline void gemmCX(const float* A1, const float* A2, const float* B1, const float* B2,
                          float* C, const float* bias1, const float* bias2,
                          int M, int N, int Kd, int lda, int ldb, int ldc,
                          long long sA, long long sB, long long sC, long long sCp,
                          int nbatch, int nzc, float alpha, float beta, bool tb) {
    dim3 grid((N + 127) / 128, (M + 127) / 128, nbatch * nzc);
    if (tb)
        gemm_cx<true><<<grid, 256>>>(A1, A2, B1, B2, C, bias1, bias2, M, N, Kd, lda, ldb, ldc,
                                     sA, sB, sC, sCp, alpha, beta, nzc);
    else
        gemm_cx<false><<<grid, 256>>>(A1, A2, B1, B2, C, bias1, bias2, M, N, Kd, lda, ldb, ldc,
                                      sA, sB, sC, sCp, alpha, beta, nzc);
}

extern "C" void kernel_launch(void* const* d_in, const int* in_sizes, int n_in,
                              void* d_out, int out_size) {
    const float* x_real = (const float*)d_in[0];
    const float* x_imag = (const float*)d_in[1];
    const float* Wq = (const float*)d_in[2];
    const float* bq = (const float*)d_in[3];
    const float* Wk = (const float*)d_in[4];
    const float* bk = (const float*)d_in[5];
    const float* Wv = (const float*)d_in[6];
    const float* bv = (const float*)d_in[7];
    const float* pk = (const float*)d_in[8];
    const float* pv = (const float*)d_in[9];
    const float* Wout = (const float*)d_in[10];
    const float* bout = (const float*)d_in[11];
    const float* W1r = (const float*)d_in[12];
    const float* W1i = (const float*)d_in[13];
    const float* b1r = (const float*)d_in[14];
    const float* b1i = (const float*)d_in[15];
    const float* W2r = (const float*)d_in[16];
    const float* W2i = (const float*)d_in[17];
    const float* b2r = (const float*)d_in[18];
    const float* b2i = (const float*)d_in[19];

    float* xr = (float*)d_out;
    float* xi = xr + ND;

    float *N_, *QKV, *P4, *D_, *O_, *H_, *PSUM;
    cudaGetSymbolAddress((void**)&N_, g_N);
    cudaGetSymbolAddress((void**)&QKV, g_QKV);
    cudaGetSymbolAddress((void**)&P4, g_P4);
    cudaGetSymbolAddress((void**)&D_, g_D);
    cudaGetSymbolAddress((void**)&O_, g_O);
    cudaGetSymbolAddress((void**)&H_, g_H);
    cudaGetSymbolAddress((void**)&PSUM, g_PSUM);

    cudaMemcpyAsync(xr, x_real, ND * sizeof(float), cudaMemcpyDeviceToDevice, 0);
    cudaMemcpyAsync(xi, x_imag, ND * sizeof(float), cudaMemcpyDeviceToDevice, 0);

    for (int d = 0; d < 2; d++) {
        const float* Wq_d = Wq + (size_t)d * D_MODEL * D_MODEL;
        const float* bq_d = bq + (size_t)d * D_MODEL;
        const float* Wk_d = Wk + (size_t)d * D_MODEL * D_MODEL;
        const float* bk_d = bk + (size_t)d * D_MODEL;
        const float* Wv_d = Wv + (size_t)d * D_MODEL * D_MODEL;
        const float* bv_d = bv + (size_t)d * D_MODEL;
        const float* pk_d = pk + (size_t)d * N_TOK * K_LR;
        const float* pv_d = pv + (size_t)d * N_TOK * K_LR;
        const float* Wo_d = Wout + (size_t)d * D_MODEL * D_MODEL;
        const float* bo_d = bout + (size_t)d * D_MODEL;
        const float* W1r_d = W1r + (size_t)d * D_MODEL * D_FF;
        const float* W1i_d = W1i + (size_t)d * D_MODEL * D_FF;
        const float* b1r_d = b1r + (size_t)d * D_FF;
        const float* b1i_d = b1i + (size_t)d * D_FF;
        const float* W2r_d = W2r + (size_t)d * D_FF * D_MODEL;
        const float* W2i_d = W2i + (size_t)d * D_FF * D_MODEL;
        const float* b2r_d = b2r + (size_t)d * D_MODEL;
        const float* b2i_d = b2i + (size_t)d * D_MODEL;

        // ---- LN1 -> g_N (NR, NI)
        cln_kernel<<<N_TOK, 512>>>(xr, xi, N_, N_ + ND);

        // ---- QKV: 3 launches, each z=2 (real/imag share weight)
        gemmCX(N_, nullptr, Wq_d, nullptr, QKV + 0 * ND, bq_d, nullptr,
               N_TOK, D_MODEL, D_MODEL, D_MODEL, D_MODEL, D_MODEL, ND, 0, ND, 0, 2, 1, 1.f, 0.f, false);
        gemmCX(N_, nullptr, Wk_d, nullptr, QKV + 2 * ND, bk_d, nullptr,
               N_TOK, D_MODEL, D_MODEL, D_MODEL, D_MODEL, D_MODEL, ND, 0, ND, 0, 2, 1, 1.f, 0.f, false);
        gemmCX(N_, nullptr, Wv_d, nullptr, QKV + 4 * ND, bv_d, nullptr,
               N_TOK, D_MODEL, D_MODEL, D_MODEL, D_MODEL, D_MODEL, ND, 0, ND, 0, 2, 1, 1.f, 0.f, false);

        // ---- low-rank projections: one launch, z=128
        {
            dim3 g(D_MODEL / 128, K_LR / 128, 4 * NSPLIT);
            proj_splitk_tc<<<g, 256>>>(pk_d, pv_d, QKV + 2 * ND, PSUM);
            proj_reduce_kernel<<<(K_LR * D_MODEL + 255) / 256, 256>>>(PSUM, P4);
        }

        // ---- complex dots: one launch, z = 8 heads x 2 parts
        gemmCX(QKV, QKV + ND, P4, P4 + KD, D_, nullptr, nullptr,
               N_TOK, K_LR, DHEAD, D_MODEL, D_MODEL, K_LR,
               DHEAD, DHEAD, NK, HNK, H_HEADS, 2, ATTN_SCALE, 0.f, true);

        // ---- complex attn out: one launch, z = 8 heads x 2 parts
        gemmCX(D_, D_ + HNK, P4 + 2 * KD, P4 + 3 * KD, O_, nullptr, nullptr,
               N_TOK, DHEAD, K_LR, K_LR, D_MODEL, D_MODEL,
               NK, DHEAD, DHEAD, ND, H_HEADS, 2, 1.f, 0.f, false);

        // ---- output projection + residual: z=2 (xr, xi contiguous in d_out)
        gemmCX(O_, nullptr, Wo_d, nullptr, xr, bo_d, nullptr,
               N_TOK, D_MODEL, D_MODEL, D_MODEL, D_MODEL, D_MODEL, ND, 0, ND, 0, 2, 1, 1.f, 1.f, false);

        // ---- LN2 -> g_N
        cln_kernel<<<N_TOK, 512>>>(xr, xi, N_, N_ + ND);

        // ---- complex FFN layer 1: one launch z=2 (HR, HI)
        gemmCX(N_, N_ + ND, W1r_d, W1i_d, H_, b1r_d, b1i_d,
               N_TOK, D_FF, D_MODEL, D_MODEL, D_FF, D_FF,
               0, 0, 0, NFF, 1, 2, 1.f, 0.f, false);
        relu_kernel<<<4096, 256>>>(H_, 2 * NFF);

        // ---- complex FFN layer 2 + residual: one launch z=2
        gemmCX(H_, H_ + NFF, W2r_d, W2i_d, xr, b2r_d, b2i_d,
               N_TOK, D_MODEL, D_FF, D_FF, D_MODEL, D_MODEL,
               0, 0, 0, ND, 1, 2, 1.f, 1.f, false);
    }
}

// round 5
// speedup vs baseline: 2.9686x; 1.0997x over previous
#include <cuda_runtime.h>
#include <cstdint>

#define N_TOK 4096
#define D_MODEL 512
#define K_LR 256
#define H_HEADS 8
#define DHEAD 64
#define D_FF 2048
#define EPS_LN 1e-5f
#define ATTN_SCALE 0.125f
#define NSPLIT 32
#define KT 16

#define ND ((long long)N_TOK * D_MODEL)
#define KD ((long long)K_LR * D_MODEL)
#define NK ((long long)N_TOK * K_LR)
#define HNK ((long long)H_HEADS * N_TOK * K_LR)
#define NFF ((long long)N_TOK * D_FF)

// ---------------- scratch (device globals: allocation-free) ----------------
__device__ float g_N[2 * N_TOK * D_MODEL];
__device__ float g_QKV[6 * N_TOK * D_MODEL];
__device__ float g_P4[4 * K_LR * D_MODEL];
__device__ float g_D[(size_t)2 * H_HEADS * N_TOK * K_LR];
__device__ float g_O[2 * N_TOK * D_MODEL];
__device__ float g_H[(size_t)2 * N_TOK * D_FF];
__device__ float g_PSUM[(size_t)4 * NSPLIT * K_LR * D_MODEL];

// ---------------- bf16 split helpers ----------------
__device__ __forceinline__ unsigned packbf(float x0, float x1) {
    unsigned r;
    asm("cvt.rn.bf16x2.f32 %0, %1, %2;" : "=r"(r) : "f"(x1), "f"(x0));
    return r;
}
__device__ __forceinline__ void split2(float x0, float x1, unsigned& hi, unsigned& lo) {
    hi = packbf(x0, x1);
    float h0 = __uint_as_float(hi << 16);
    float h1 = __uint_as_float(hi & 0xffff0000u);
    lo = packbf(x0 - h0, x1 - h1);
}
__device__ __forceinline__ void mma_bf16(float* c, const unsigned* a, const unsigned* b) {
    asm volatile(
        "mma.sync.aligned.m16n8k16.row.col.f32.bf16.bf16.f32 "
        "{%0,%1,%2,%3}, {%4,%5,%6,%7}, {%8,%9}, {%0,%1,%2,%3};\n"
        : "+f"(c[0]), "+f"(c[1]), "+f"(c[2]), "+f"(c[3])
        : "r"(a[0]), "r"(a[1]), "r"(a[2]), "r"(a[3]), "r"(b[0]), "r"(b[1]));
}
__device__ __forceinline__ void ldm4(unsigned* r, unsigned addr) {
    asm volatile(
        "ldmatrix.sync.aligned.m8n8.x4.shared.b16 {%0,%1,%2,%3}, [%4];"
        : "=r"(r[0]), "=r"(r[1]), "=r"(r[2]), "=r"(r[3])
        : "r"(addr));
}

// ---------------- block reduction ----------------
__device__ __forceinline__ float blockSum(float v, float* red) {
#pragma unroll
    for (int o = 16; o > 0; o >>= 1) v += __shfl_xor_sync(0xffffffffu, v, o);
    int lane = threadIdx.x & 31, w = threadIdx.x >> 5;
    if (lane == 0) red[w] = v;
    __syncthreads();
    if (w == 0) {
        float x = (lane < 16) ? red[lane] : 0.f;
#pragma unroll
        for (int o = 8; o > 0; o >>= 1) x += __shfl_xor_sync(0xffffffffu, x, o);
        if (lane == 0) red[0] = x;
    }
    __syncthreads();
    float r = red[0];
    __syncthreads();
    return r;
}

// ---------------- complex layernorm (whitening) ----------------
__global__ void cln_kernel(const float* __restrict__ xr, const float* __restrict__ xi,
                           float* __restrict__ nr, float* __restrict__ ni) {
    __shared__ float red[16];
    int row = blockIdx.x;
    int t = threadIdx.x;
    long long base = (long long)row * D_MODEL;
    float vr = xr[base + t];
    float vi = xi[base + t];
    const float invD = 1.0f / D_MODEL;
    float mr = blockSum(vr, red) * invD;
    float mi = blockSum(vi, red) * invD;
    float cr = vr - mr, ci = vi - mi;
    float Crr = blockSum(cr * cr, red) * invD + EPS_LN;
    float Cii = blockSum(ci * ci, red) * invD + EPS_LN;
    float Cri = blockSum(cr * ci, red) * invD;
    float s = sqrtf(Crr * Cii - Cri * Cri);
    float tt = sqrtf(Cii + Crr + 2.0f * s);
    float inv = 1.0f / (s * tt);
    float Rrr = (Cii + s) * inv;
    float Rii = (Crr + s) * inv;
    float Rri = -Cri * inv;
    nr[base + t] = Rrr * cr + Rri * ci;
    ni[base + t] = Rii * ci + Rri * cr;
}

// ---------------- bf16x3 complex/chained TC GEMM with ldmatrix ----------------
// Unified smem layout for A and B: [row 0..127][kpair 0..7] b32, 16B-group swizzle:
//   position_of_group(g,row) = g ^ ((row>>2)&1)   (g = k-half 0/1, 16B each)
// nzc==1: C[z] = beta*C + alpha*A1[z]@op(B1[z]) + bias1
// nzc==2: part0: C = beta*C + alpha*(A1@B1 - A2@B2) + bias1
//         part1: C = beta*C + alpha*(A1@B2 + A2@B1) + bias2
template <bool TB>
__global__ void __launch_bounds__(256, 2) gemm_cx(
    const float* __restrict__ A1, const float* __restrict__ A2,
    const float* __restrict__ B1, const float* __restrict__ B2,
    float* __restrict__ C, const float* __restrict__ bias1, const float* __restrict__ bias2,
    int M, int N, int Kd, int lda, int ldb, int ldc,
    long long sA, long long sB, long long sC, long long sCp,
    float alpha, float beta, int nzc) {
    // [buf][hi/lo][128*8]
    __shared__ unsigned As[2][2][128 * 8];
    __shared__ unsigned Bs[2][2][128 * 8];

    const int z = blockIdx.z;
    const int part = (nzc == 2) ? (z & 1) : 0;
    const int bz = (nzc == 2) ? (z >> 1) : z;

    const float* Au0 = A1 + (long long)bz * sA;
    const float* Au1 = A2 ? A2 + (long long)bz * sA : nullptr;
    const float* Bu0;
    const float* Bu1 = nullptr;
    float s2 = 1.f;
    const float* biasz;
    if (part == 0) {
        Bu0 = B1 + (long long)bz * sB;
        if (A2) Bu1 = B2 + (long long)bz * sB;
        s2 = -1.f;
        biasz = bias1;
    } else {
        Bu0 = B2 + (long long)bz * sB;
        Bu1 = B1 + (long long)bz * sB;
        s2 = 1.f;
        biasz = bias2;
    }
    float* Cb = C + (long long)bz * sC + (long long)part * sCp;

    const int brow = blockIdx.y * 128, bcol = blockIdx.x * 128;
    const int tid = threadIdx.x;
    const int lane = tid & 31, w = tid >> 5;
    const int wr = w >> 2, wc = w & 3;
    const int gr = lane >> 2, gc = lane & 3;

    float acc[4][4][4];
#pragma unroll
    for (int i = 0; i < 4; i++)
#pragma unroll
        for (int j = 0; j < 4; j++)
#pragma unroll
            for (int q = 0; q < 4; q++) acc[i][j][q] = 0.f;

    // ---- loader indices
    const int am = tid >> 1, kh = tid & 1;                 // A / TB-B loader
    const unsigned a_soff = am * 8 + ((kh ^ ((am >> 2) & 1)) * 4);
    const int bnr = tid & 127, bkh = tid >> 7;             // non-TB B loader
    const unsigned b_soff = bnr * 8 + ((bkh ^ ((bnr >> 2) & 1)) * 4);

    // ---- ldmatrix lane addressing
    const int lm_row = ((lane >> 3) & 1) * 8 + (lane & 7);
    const int lm_g = lane >> 4;
    const int a_mb = wr * 64 + lm_row;
    const unsigned a_frag = (a_mb * 8 + ((lm_g ^ ((a_mb >> 2) & 1)) * 4)) * 4;  // bytes
    const int b_nb = wc * 32 + lm_row;
    const unsigned b_frag = (b_nb * 8 + ((lm_g ^ ((b_nb >> 2) & 1)) * 4)) * 4;

    const unsigned asb = (unsigned)__cvta_generic_to_shared(&As[0][0][0]);
    const unsigned bsb = (unsigned)__cvta_generic_to_shared(&Bs[0][0][0]);

    float4 pa0, pa1, pb0, pb1;
    float vb[8];
    float psg = 1.f;

    const int ntile1 = Kd / KT;
    const int ntot = (A2 ? 2 : 1) * ntile1;

    auto ld = [&](int t) {
        int ch = (t >= ntile1);
        const float* Ab = ch ? Au1 : Au0;
        const float* Bb = ch ? Bu1 : Bu0;
        psg = ch ? s2 : 1.f;
        int k0 = (ch ? t - ntile1 : t) * KT;
        {
            const float* p = &Ab[(long long)(brow + am) * lda + k0 + kh * 8];
            pa0 = *(const float4*)p;
            pa1 = *(const float4*)(p + 4);
        }
        if (TB) {
            int gn = bcol + am;
            if (gn < N) {
                const float* p = &Bb[(long long)gn * ldb + k0 + kh * 8];
                pb0 = *(const float4*)p;
                pb1 = *(const float4*)(p + 4);
            } else {
                pb0 = make_float4(0.f, 0.f, 0.f, 0.f);
                pb1 = pb0;
            }
        } else {
            int gn = bcol + bnr;
            if (gn < N) {
#pragma unroll
                for (int j = 0; j < 8; j++)
                    vb[j] = Bb[(long long)(k0 + bkh * 8 + j) * ldb + gn];
            } else {
#pragma unroll
                for (int j = 0; j < 8; j++) vb[j] = 0.f;
            }
        }
    };
    auto stAB = [&](int buf) {
        {
            uint4 h, l;
            split2(pa0.x, pa0.y, h.x, l.x);
            split2(pa0.z, pa0.w, h.y, l.y);
            split2(pa1.x, pa1.y, h.z, l.z);
            split2(pa1.z, pa1.w, h.w, l.w);
            *(uint4*)&As[buf][0][a_soff] = h;
            *(uint4*)&As[buf][1][a_soff] = l;
        }
        float sg = psg;
        if (TB) {
            uint4 h, l;
            split2(sg * pb0.x, sg * pb0.y, h.x, l.x);
            split2(sg * pb0.z, sg * pb0.w, h.y, l.y);
            split2(sg * pb1.x, sg * pb1.y, h.z, l.z);
            split2(sg * pb1.z, sg * pb1.w, h.w, l.w);
            *(uint4*)&Bs[buf][0][a_soff] = h;
            *(uint4*)&Bs[buf][1][a_soff] = l;
        } else {
            uint4 h, l;
            split2(sg * vb[0], sg * vb[1], h.x, l.x);
            split2(sg * vb[2], sg * vb[3], h.y, l.y);
            split2(sg * vb[4], sg * vb[5], h.z, l.z);
            split2(sg * vb[6], sg * vb[7], h.w, l.w);
            *(uint4*)&Bs[buf][0][b_soff] = h;
            *(uint4*)&Bs[buf][1][b_soff] = l;
        }
    };
    auto compute = [&](int buf) {
        unsigned bufA = asb + buf * 8192;
        unsigned bufB = bsb + buf * 8192;
        unsigned bh[4][2], bl[4][2];
#pragma unroll
        for (int p = 0; p < 2; p++) {
            unsigned r[4];
            ldm4(r, bufB + b_frag + p * 512);
            bh[2 * p][0] = r[0]; bh[2 * p + 1][0] = r[1];
            bh[2 * p][1] = r[2]; bh[2 * p + 1][1] = r[3];
            ldm4(r, bufB + 4096 + b_frag + p * 512);
            bl[2 * p][0] = r[0]; bl[2 * p + 1][0] = r[1];
            bl[2 * p][1] = r[2]; bl[2 * p + 1][1] = r[3];
        }
#pragma unroll
        for (int mt = 0; mt < 4; mt++) {
            unsigned ah[4], al[4];
            ldm4(ah, bufA + a_frag + mt * 512);
            ldm4(al, bufA + 4096 + a_frag + mt * 512);
#pragma unroll
            for (int nt = 0; nt < 4; nt++) {
                mma_bf16(acc[mt][nt], ah, bh[nt]);
                mma_bf16(acc[mt][nt], al, bh[nt]);
                mma_bf16(acc[mt][nt], ah, bl[nt]);
            }
        }
    };

    ld(0);
    stAB(0);
    __syncthreads();
    for (int t = 0; t < ntot; t++) {
        if (t + 1 < ntot) ld(t + 1);
        compute(t & 1);
        if (t + 1 < ntot) stAB((t + 1) & 1);
        __syncthreads();
    }

#pragma unroll
    for (int mt = 0; mt < 4; mt++) {
        int m0 = brow + wr * 64 + mt * 16 + gr;
#pragma unroll
        for (int nt = 0; nt < 4; nt++) {
            int n0 = bcol + wc * 32 + nt * 8 + gc * 2;
            if (n0 < N) {
                const float* c = acc[mt][nt];
                long long off = (long long)m0 * ldc + n0;
                float2 v;
                v.x = alpha * c[0];
                v.y = alpha * c[1];
                if (beta != 0.f) {
                    float2 o = *(const float2*)&Cb[off];
                    v.x += beta * o.x;
                    v.y += beta * o.y;
                }
                if (biasz) {
                    v.x += biasz[n0];
                    v.y += biasz[n0 + 1];
                }
                *(float2*)&Cb[off] = v;
                off += (long long)8 * ldc;
                v.x = alpha * c[2];
                v.y = alpha * c[3];
                if (beta != 0.f) {
                    float2 o = *(const float2*)&Cb[off];
                    v.x += beta * o.x;
                    v.y += beta * o.y;
                }
                if (biasz) {
                    v.x += biasz[n0];
                    v.y += biasz[n0 + 1];
                }
                *(float2*)&Cb[off] = v;
            }
        }
    }
}

// ---------------- split-K projection (bf16x3): all 4 proj GEMMs in one launch ----
__global__ void __launch_bounds__(256, 2) proj_splitk_tc(
    const float* __restrict__ pk, const float* __restrict__ pv,
    const float* __restrict__ KV, float* __restrict__ P) {
    __shared__ unsigned As[2][2][8 * 136];
    __shared__ unsigned Bs[2][2][8 * 136];
    const int z = blockIdx.z;
    const int p = z >> 5;
    const int s = z & 31;
    const float* A = (p < 2) ? pk : pv;
    const float* B = KV + (long long)p * ND;
    const int chunk = N_TOK / NSPLIT;
    const int kbeg = s * chunk;
    const int brow = blockIdx.y * 128, bcol = blockIdx.x * 128;
    const int tid = threadIdx.x;
    const int lane = tid & 31, w = tid >> 5;
    const int wr = w >> 2, wc = w & 3;
    const int gr = lane >> 2, gc = lane & 3;
    const int kp = tid >> 5;
    const int an = lane * 4;

    float acc[4][4][4];
#pragma unroll
    for (int i = 0; i < 4; i++)
#pragma unroll
        for (int j = 0; j < 4; j++)
#pragma unroll
            for (int q = 0; q < 4; q++) acc[i][j][q] = 0.f;

    float4 pa0, pa1, pb0, pb1;
    auto ld = [&](int k0) {
        pa0 = *(const float4*)&A[(long long)(k0 + 2 * kp) * K_LR + brow + an];
        pa1 = *(const float4*)&A[(long long)(k0 + 2 * kp + 1) * K_LR + brow + an];
        pb0 = *(const float4*)&B[(long long)(k0 + 2 * kp) * D_MODEL + bcol + an];
        pb1 = *(const float4*)&B[(long long)(k0 + 2 * kp + 1) * D_MODEL + bcol + an];
    };
    auto st = [&](int buf) {
        unsigned h, l;
        unsigned base = kp * 136 + an;
        split2(pa0.x, pa1.x, h, l); As[buf][0][base + 0] = h; As[buf][1][base + 0] = l;
        split2(pa0.y, pa1.y, h, l); As[buf][0][base + 1] = h; As[buf][1][base + 1] = l;
        split2(pa0.z, pa1.z, h, l); As[buf][0][base + 2] = h; As[buf][1][base + 2] = l;
        split2(pa0.w, pa1.w, h, l); As[buf][0][base + 3] = h; As[buf][1][base + 3] = l;
        split2(pb0.x, pb1.x, h, l); Bs[buf][0][base + 0] = h; Bs[buf][1][base + 0] = l;
        split2(pb0.y, pb1.y, h, l); Bs[buf][0][base + 1] = h; Bs[buf][1][base + 1] = l;
        split2(pb0.z, pb1.z, h, l); Bs[buf][0][base + 2] = h; Bs[buf][1][base + 2] = l;
        split2(pb0.w, pb1.w, h, l); Bs[buf][0][base + 3] = h; Bs[buf][1][base + 3] = l;
    };
    auto compute = [&](int buf) {
        unsigned bh[4][2], bl[4][2];
#pragma unroll
        for (int nt = 0; nt < 4; nt++) {
            int n = wc * 32 + nt * 8 + gr;
            bh[nt][0] = Bs[buf][0][gc * 136 + n];
            bh[nt][1] = Bs[buf][0][(gc + 4) * 136 + n];
            bl[nt][0] = Bs[buf][1][gc * 136 + n];
            bl[nt][1] = Bs[buf][1][(gc + 4) * 136 + n];
        }
#pragma unroll
        for (int mt = 0; mt < 4; mt++) {
            int m = wr * 64 + mt * 16;
            unsigned ah[4], al[4];
            ah[0] = As[buf][0][gc * 136 + m + gr];
            ah[1] = As[buf][0][gc * 136 + m + 8 + gr];
            ah[2] = As[buf][0][(gc + 4) * 136 + m + gr];
            ah[3] = As[buf][0][(gc + 4) * 136 + m + 8 + gr];
            al[0] = As[buf][1][gc * 136 + m + gr];
            al[1] = As[buf][1][gc * 136 + m + 8 + gr];
            al[2] = As[buf][1][(gc + 4) * 136 + m + gr];
            al[3] = As[buf][1][(gc + 4) * 136 + m + 8 + gr];
#pragma unroll
            for (int nt = 0; nt < 4; nt++) {
                mma_bf16(acc[mt][nt], ah, bh[nt]);
                mma_bf16(acc[mt][nt], al, bh[nt]);
                mma_bf16(acc[mt][nt], ah, bl[nt]);
            }
        }
    };

    ld(kbeg);
    st(0);
    __syncthreads();
    const int ntile = chunk / KT;
    for (int t = 0; t < ntile; t++) {
        if (t + 1 < ntile) ld(kbeg + (t + 1) * KT);
        compute(t & 1);
        if (t + 1 < ntile) st((t + 1) & 1);
        __syncthreads();
    }

    float* Pz = P + (long long)z * KD;
#pragma unroll
    for (int mt = 0; mt < 4; mt++) {
        int m0 = brow + wr * 64 + mt * 16 + gr;
#pragma unroll
        for (int nt = 0; nt < 4; nt++) {
            int n0 = bcol + wc * 32 + nt * 8 + gc * 2;
            const float* c = acc[mt][nt];
            *(float2*)&Pz[(long long)m0 * D_MODEL + n0] = make_float2(c[0], c[1]);
            *(float2*)&Pz[(long long)(m0 + 8) * D_MODEL + n0] = make_float2(c[2], c[3]);
        }
    }
}

__global__ void proj_reduce_kernel(const float* __restrict__ P, float* __restrict__ P4) {
    const int n = K_LR * D_MODEL;
    int i = blockIdx.x * blockDim.x + threadIdx.x;
    if (i >= n) return;
#pragma unroll
    for (int p = 0; p < 4; p++) {
        const float* base = P + (long long)p * NSPLIT * n + i;
        float s = 0.f;
#pragma unroll
        for (int zz = 0; zz < NSPLIT; zz++) s += base[(long long)zz * n];
        P4[(long long)p * n + i] = s;
    }
}

__global__ void relu_kernel(float* __restrict__ a, long long n) {
    long long i = (long long)blockIdx.x * blockDim.x + threadIdx.x;
    long long stride = (long long)gridDim.x * blockDim.x;
    for (; i < n; i += stride) a[i] = fmaxf(a[i], 0.f);
}

// ---------------- host launcher ----------------
static inline void gemmCX(const float* A1, const float* A2, const float* B1, const float* B2,
                          float* C, const float* bias1, const float* bias2,
                          int M, int N, int Kd, int lda, int ldb, int ldc,
                          long long sA, long long sB, long long sC, long long sCp,
                          int nbatch, int nzc, float alpha, float beta, bool tb) {
    dim3 grid((N + 127) / 128, (M + 127) / 128, nbatch * nzc);
    if (tb)
        gemm_cx<true><<<grid, 256>>>(A1, A2, B1, B2, C, bias1, bias2, M, N, Kd, lda, ldb, ldc,
                                     sA, sB, sC, sCp, alpha, beta, nzc);
    else
        gemm_cx<false><<<grid, 256>>>(A1, A2, B1, B2, C, bias1, bias2, M, N, Kd, lda, ldb, ldc,
                                      sA, sB, sC, sCp, alpha, beta, nzc);
}

extern "C" void kernel_launch(void* const* d_in, const int* in_sizes, int n_in,
                              void* d_out, int out_size) {
    const float* x_real = (const float*)d_in[0];
    const float* x_imag = (const float*)d_in[1];
    const float* Wq = (const float*)d_in[2];
    const float* bq = (const float*)d_in[3];
    const float* Wk = (const float*)d_in[4];
    const float* bk = (const float*)d_in[5];
    const float* Wv = (const float*)d_in[6];
    const float* bv = (const float*)d_in[7];
    const float* pk = (const float*)d_in[8];
    const float* pv = (const float*)d_in[9];
    const float* Wout = (const float*)d_in[10];
    const float* bout = (const float*)d_in[11];
    const float* W1r = (const float*)d_in[12];
    const float* W1i = (const float*)d_in[13];
    const float* b1r = (const float*)d_in[14];
    const float* b1i = (const float*)d_in[15];
    const float* W2r = (const float*)d_in[16];
    const float* W2i = (const float*)d_in[17];
    const float* b2r = (const float*)d_in[18];
    const float* b2i = (const float*)d_in[19];

    float* xr = (float*)d_out;
    float* xi = xr + ND;

    float *N_, *QKV, *P4, *D_, *O_, *H_, *PSUM;
    cudaGetSymbolAddress((void**)&N_, g_N);
    cudaGetSymbolAddress((void**)&QKV, g_QKV);
    cudaGetSymbolAddress((void**)&P4, g_P4);
    cudaGetSymbolAddress((void**)&D_, g_D);
    cudaGetSymbolAddress((void**)&O_, g_O);
    cudaGetSymbolAddress((void**)&H_, g_H);
    cudaGetSymbolAddress((void**)&PSUM, g_PSUM);

    cudaMemcpyAsync(xr, x_real, ND * sizeof(float), cudaMemcpyDeviceToDevice, 0);
    cudaMemcpyAsync(xi, x_imag, ND * sizeof(float), cudaMemcpyDeviceToDevice, 0);

    for (int d = 0; d < 2; d++) {
        const float* Wq_d = Wq + (size_t)d * D_MODEL * D_MODEL;
        const float* bq_d = bq + (size_t)d * D_MODEL;
        const float* Wk_d = Wk + (size_t)d * D_MODEL * D_MODEL;
        const float* bk_d = bk + (size_t)d * D_MODEL;
        const float* Wv_d = Wv + (size_t)d * D_MODEL * D_MODEL;
        const float* bv_d = bv + (size_t)d * D_MODEL;
        const float* pk_d = pk + (size_t)d * N_TOK * K_LR;
        const float* pv_d = pv + (size_t)d * N_TOK * K_LR;
        const float* Wo_d = Wout + (size_t)d * D_MODEL * D_MODEL;
        const float* bo_d = bout + (size_t)d * D_MODEL;
        const float* W1r_d = W1r + (size_t)d * D_MODEL * D_FF;
        const float* W1i_d = W1i + (size_t)d * D_MODEL * D_FF;
        const float* b1r_d = b1r + (size_t)d * D_FF;
        const float* b1i_d = b1i + (size_t)d * D_FF;
        const float* W2r_d = W2r + (size_t)d * D_FF * D_MODEL;
        const float* W2i_d = W2i + (size_t)d * D_FF * D_MODEL;
        const float* b2r_d = b2r + (size_t)d * D_MODEL;
        const float* b2i_d = b2i + (size_t)d * D_MODEL;

        // ---- LN1
        cln_kernel<<<N_TOK, 512>>>(xr, xi, N_, N_ + ND);

        // ---- QKV (z=2: real/imag share weights)
        gemmCX(N_, nullptr, Wq_d, nullptr, QKV + 0 * ND, bq_d, nullptr,
               N_TOK, D_MODEL, D_MODEL, D_MODEL, D_MODEL, D_MODEL, ND, 0, ND, 0, 2, 1, 1.f, 0.f, false);
        gemmCX(N_, nullptr, Wk_d, nullptr, QKV + 2 * ND, bk_d, nullptr,
               N_TOK, D_MODEL, D_MODEL, D_MODEL, D_MODEL, D_MODEL, ND, 0, ND, 0, 2, 1, 1.f, 0.f, false);
        gemmCX(N_, nullptr, Wv_d, nullptr, QKV + 4 * ND, bv_d, nullptr,
               N_TOK, D_MODEL, D_MODEL, D_MODEL, D_MODEL, D_MODEL, ND, 0, ND, 0, 2, 1, 1.f, 0.f, false);

        // ---- low-rank projections: one launch, z=128
        {
            dim3 g(D_MODEL / 128, K_LR / 128, 4 * NSPLIT);
            proj_splitk_tc<<<g, 256>>>(pk_d, pv_d, QKV + 2 * ND, PSUM);
            proj_reduce_kernel<<<(K_LR * D_MODEL + 255) / 256, 256>>>(PSUM, P4);
        }

        // ---- complex dots: z = 8 heads x 2 parts
        gemmCX(QKV, QKV + ND, P4, P4 + KD, D_, nullptr, nullptr,
               N_TOK, K_LR, DHEAD, D_MODEL, D_MODEL, K_LR,
               DHEAD, DHEAD, NK, HNK, H_HEADS, 2, ATTN_SCALE, 0.f, true);

        // ---- complex attn out: z = 8 heads x 2 parts
        gemmCX(D_, D_ + HNK, P4 + 2 * KD, P4 + 3 * KD, O_, nullptr, nullptr,
               N_TOK, DHEAD, K_LR, K_LR, D_MODEL, D_MODEL,
               NK, DHEAD, DHEAD, ND, H_HEADS, 2, 1.f, 0.f, false);

        // ---- output projection + residual: z=2
        gemmCX(O_, nullptr, Wo_d, nullptr, xr, bo_d, nullptr,
               N_TOK, D_MODEL, D_MODEL, D_MODEL, D_MODEL, D_MODEL, ND, 0, ND, 0, 2, 1, 1.f, 1.f, false);

        // ---- LN2
        cln_kernel<<<N_TOK, 512>>>(xr, xi, N_, N_ + ND);

        // ---- complex FFN layer 1: z=2
        gemmCX(N_, N_ + ND, W1r_d, W1i_d, H_, b1r_d, b1i_d,
               N_TOK, D_FF, D_MODEL, D_MODEL, D_FF, D_FF,
               0, 0, 0, NFF, 1, 2, 1.f, 0.f, false);
        relu_kernel<<<4096, 256>>>(H_, 2 * NFF);

        // ---- complex FFN layer 2 + residual: z=2
        gemmCX(H_, H_ + NFF, W2r_d, W2i_d, xr, b2r_d, b2i_d,
               N_TOK, D_MODEL, D_FF, D_FF, D_MODEL, D_MODEL,
               0, 0, 0, ND, 1, 2, 1.f, 1.f, false);
    }
}

// round 6
// speedup vs baseline: 3.0368x; 1.0230x over previous
#include <cuda_runtime.h>
#include <cstdint>

#define N_TOK 4096
#define D_MODEL 512
#define K_LR 256
#define H_HEADS 8
#define DHEAD 64
#define D_FF 2048
#define EPS_LN 1e-5f
#define ATTN_SCALE 0.125f
#define NSPLIT 32
#define KT 16

#define ND ((long long)N_TOK * D_MODEL)
#define KD ((long long)K_LR * D_MODEL)
#define NK ((long long)N_TOK * K_LR)
#define HNK ((long long)H_HEADS * NK)
#define NFF ((long long)N_TOK * D_FF)

#define NDH 1048576LL   /* ND/2  */
#define KDH 65536LL     /* KD/2  */
#define NKH 524288LL    /* NK/2  */
#define HNKH 4194304LL  /* HNK/2 */
#define NFFH 4194304LL  /* NFF/2 */

// ---------------- scratch (device globals: allocation-free) ----------------
// split arrays: blocks [r_hi | r_lo | i_hi | i_lo]
__device__ unsigned g_Nsp[4 * NDH];
__device__ unsigned g_Qsp[4 * NDH];
__device__ float    g_KVf[4 * ND];         // KR,KI,VR,VI (fp32, feeds proj)
__device__ unsigned g_KPsp[4 * KDH];       // TB layout: [K_LR][D/2] pairs along D
__device__ unsigned g_VPsp[4 * KDH];       // nonTB layout: [K_LR/2][D] pairs along K
__device__ unsigned g_Dsp[4 * HNKH];
__device__ unsigned g_Osp[4 * NDH];
__device__ unsigned g_Hsp[4 * NFFH];
__device__ float    g_PSUM[4 * NSPLIT * KD];
// pre-split weights: [depth][w][hi/lo][halfK*N]
__device__ unsigned g_Wq[2 * 2 * 131072];
__device__ unsigned g_Wk[2 * 2 * 131072];
__device__ unsigned g_Wv[2 * 2 * 131072];
__device__ unsigned g_Wo[2 * 2 * 131072];
__device__ unsigned g_W1r[2 * 2 * 524288];
__device__ unsigned g_W1i[2 * 2 * 524288];
__device__ unsigned g_W2r[2 * 2 * 524288];
__device__ unsigned g_W2i[2 * 2 * 524288];

// ---------------- bf16 split helpers ----------------
__device__ __forceinline__ unsigned packbf(float x0, float x1) {
    unsigned r;
    asm("cvt.rn.bf16x2.f32 %0, %1, %2;" : "=r"(r) : "f"(x1), "f"(x0));
    return r;
}
__device__ __forceinline__ void split2(float x0, float x1, unsigned& hi, unsigned& lo) {
    hi = packbf(x0, x1);
    float h0 = __uint_as_float(hi << 16);
    float h1 = __uint_as_float(hi & 0xffff0000u);
    lo = packbf(x0 - h0, x1 - h1);
}
__device__ __forceinline__ void mma_bf16(float* c, const unsigned* a, const unsigned* b) {
    asm volatile(
        "mma.sync.aligned.m16n8k16.row.col.f32.bf16.bf16.f32 "
        "{%0,%1,%2,%3}, {%4,%5,%6,%7}, {%8,%9}, {%0,%1,%2,%3};\n"
        : "+f"(c[0]), "+f"(c[1]), "+f"(c[2]), "+f"(c[3])
        : "r"(a[0]), "r"(a[1]), "r"(a[2]), "r"(a[3]), "r"(b[0]), "r"(b[1]));
}
__device__ __forceinline__ void ldm4(unsigned* r, unsigned addr) {
    asm volatile(
        "ldmatrix.sync.aligned.m8n8.x4.shared.b16 {%0,%1,%2,%3}, [%4];"
        : "=r"(r[0]), "=r"(r[1]), "=r"(r[2]), "=r"(r[3])
        : "r"(addr));
}

// ---------------- block reduction ----------------
__device__ __forceinline__ float blockSum(float v, float* red) {
#pragma unroll
    for (int o = 16; o > 0; o >>= 1) v += __shfl_xor_sync(0xffffffffu, v, o);
    int lane = threadIdx.x & 31, w = threadIdx.x >> 5;
    if (lane == 0) red[w] = v;
    __syncthreads();
    if (w == 0) {
        float x = (lane < 16) ? red[lane] : 0.f;
#pragma unroll
        for (int o = 8; o > 0; o >>= 1) x += __shfl_xor_sync(0xffffffffu, x, o);
        if (lane == 0) red[0] = x;
    }
    __syncthreads();
    float r = red[0];
    __syncthreads();
    return r;
}

// ---------------- complex layernorm -> split bf16 output ----------------
__global__ void cln_kernel(const float* __restrict__ xr, const float* __restrict__ xi,
                           unsigned* __restrict__ Nsp) {
    __shared__ float red[16];
    int row = blockIdx.x;
    int t = threadIdx.x;
    long long base = (long long)row * D_MODEL;
    float vr = xr[base + t];
    float vi = xi[base + t];
    const float invD = 1.0f / D_MODEL;
    float mr = blockSum(vr, red) * invD;
    float mi = blockSum(vi, red) * invD;
    float cr = vr - mr, ci = vi - mi;
    float Crr = blockSum(cr * cr, red) * invD + EPS_LN;
    float Cii = blockSum(ci * ci, red) * invD + EPS_LN;
    float Cri = blockSum(cr * ci, red) * invD;
    float s = sqrtf(Crr * Cii - Cri * Cri);
    float tt = sqrtf(Cii + Crr + 2.0f * s);
    float inv = 1.0f / (s * tt);
    float Rrr = (Cii + s) * inv;
    float Rii = (Crr + s) * inv;
    float Rri = -Cri * inv;
    float outr = Rrr * cr + Rri * ci;
    float outi = Rii * ci + Rri * cr;
    float outr2 = __shfl_down_sync(0xffffffffu, outr, 1);
    float outi2 = __shfl_down_sync(0xffffffffu, outi, 1);
    if ((t & 1) == 0) {
        long long o = (long long)row * (D_MODEL / 2) + (t >> 1);
        unsigned h, l;
        split2(outr, outr2, h, l);
        Nsp[o] = h;
        Nsp[NDH + o] = l;
        split2(outi, outi2, h, l);
        Nsp[2 * NDH + o] = h;
        Nsp[3 * NDH + o] = l;
    }
}

// ---------------- pre-split TC GEMM (no cvt in mainloop) ----------------
// Operands are bf16x2-packed hi/lo arrays (pairs along k).
// A: [M][Kd/2] pairs, stride ldap. TB B: [N][Kd/2] pairs, stride ldbp.
// nonTB B: [Kd/2][N], row stride ldbp (= element N stride).
// nzc==1: C[z] = beta*C + alpha*A1[z]@op(B1[z]) + bias1
// nzc==2: part0: C = beta*C + alpha*(A1@B1 - A2@B2) + bias1
//         part1: C = beta*C + alpha*(A1@B2 + A2@B1) + bias2
// Output: fp32 Cf and/or split (Ch,Cl) pairs along n (ldc/2). Optional relu.
template <bool TB>
__global__ void __launch_bounds__(256, 2) gemm_sp(
    const unsigned* __restrict__ A1h, const unsigned* __restrict__ A1l,
    const unsigned* __restrict__ A2h, const unsigned* __restrict__ A2l,
    const unsigned* __restrict__ B1h, const unsigned* __restrict__ B1l,
    const unsigned* __restrict__ B2h, const unsigned* __restrict__ B2l,
    float* __restrict__ Cf, unsigned* __restrict__ Ch, unsigned* __restrict__ Cl,
    const float* __restrict__ bias1, const float* __restrict__ bias2,
    int M, int N, int Kd, int ldap, int ldbp, int ldc,
    long long sAp, long long sBp, long long sC, long long sCp,
    float alpha, float beta, int nzc, int dorelu) {
    __shared__ unsigned As[2][2][128 * 8];
    __shared__ unsigned Bs[2][2][128 * 8];

    const int z = blockIdx.z;
    const int part = (nzc == 2) ? (z & 1) : 0;
    const int bz = (nzc == 2) ? (z >> 1) : z;

    const unsigned* Au0h = A1h + bz * sAp;
    const unsigned* Au0l = A1l + bz * sAp;
    const unsigned* Au1h = A2h ? A2h + bz * sAp : nullptr;
    const unsigned* Au1l = A2h ? A2l + bz * sAp : nullptr;
    const unsigned *Bu0h, *Bu0l, *Bu1h = nullptr, *Bu1l = nullptr;
    const float* biasz;
    unsigned negmask;
    if (part == 0) {
        Bu0h = B1h + bz * sBp;
        Bu0l = B1l + bz * sBp;
        if (A2h) {
            Bu1h = B2h + bz * sBp;
            Bu1l = B2l + bz * sBp;
        }
        negmask = 0x80008000u;  // chunk2 negated
        biasz = bias1;
    } else {
        Bu0h = B2h + bz * sBp;
        Bu0l = B2l + bz * sBp;
        Bu1h = B1h + bz * sBp;
        Bu1l = B1l + bz * sBp;
        negmask = 0u;
        biasz = bias2;
    }
    float* Cfb = Cf ? Cf + bz * sC + (long long)part * sCp : nullptr;
    unsigned* Chb = Ch ? Ch + bz * sC + (long long)part * sCp : nullptr;
    unsigned* Clb = Ch ? Cl + bz * sC + (long long)part * sCp : nullptr;

    const int brow = blockIdx.y * 128, bcol = blockIdx.x * 128;
    const int tid = threadIdx.x;
    const int lane = tid & 31, w = tid >> 5;
    const int wr = w >> 2, wc = w & 3;
    const int gr = lane >> 2, gc = lane & 3;

    float acc[4][4][4];
#pragma unroll
    for (int i = 0; i < 4; i++)
#pragma unroll
        for (int j = 0; j < 4; j++)
#pragma unroll
            for (int q = 0; q < 4; q++) acc[i][j][q] = 0.f;

    // loader indices
    const int am = tid >> 1, kh = tid & 1;
    const unsigned a_soff = am * 8 + ((kh ^ ((am >> 2) & 1)) * 4);
    const int bnr = tid & 127, bkh = tid >> 7;
    const unsigned b_soff = bnr * 8 + ((bkh ^ ((bnr >> 2) & 1)) * 4);

    // ldmatrix lane addressing
    const int lm_row = ((lane >> 3) & 1) * 8 + (lane & 7);
    const int lm_g = lane >> 4;
    const int a_mb = wr * 64 + lm_row;
    const unsigned a_frag = (a_mb * 8 + ((lm_g ^ ((a_mb >> 2) & 1)) * 4)) * 4;
    const int b_nb = wc * 32 + lm_row;
    const unsigned b_frag = (b_nb * 8 + ((lm_g ^ ((b_nb >> 2) & 1)) * 4)) * 4;

    const unsigned asb = (unsigned)__cvta_generic_to_shared(&As[0][0][0]);
    const unsigned bsb = (unsigned)__cvta_generic_to_shared(&Bs[0][0][0]);

    uint4 pah, pal, pbh, pbl;

    const int ntile1 = Kd / KT;
    const int ntot = (A2h ? 2 : 1) * ntile1;

    auto ld = [&](int t) {
        int ch = (t >= ntile1);
        const unsigned* Abh = ch ? Au1h : Au0h;
        const unsigned* Abl = ch ? Au1l : Au0l;
        const unsigned* Bbh = ch ? Bu1h : Bu0h;
        const unsigned* Bbl = ch ? Bu1l : Bu0l;
        unsigned msk = ch ? negmask : 0u;
        int k0p = (ch ? t - ntile1 : t) * (KT / 2);
        {
            long long off = (long long)(brow + am) * ldap + k0p + kh * 4;
            pah = *(const uint4*)&Abh[off];
            pal = *(const uint4*)&Abl[off];
        }
        if (TB) {
            int gn = bcol + am;
            if (gn < N) {
                long long off = (long long)gn * ldbp + k0p + kh * 4;
                pbh = *(const uint4*)&Bbh[off];
                pbl = *(const uint4*)&Bbl[off];
            } else {
                pbh = make_uint4(0, 0, 0, 0);
                pbl = pbh;
            }
        } else {
            int gn = bcol + bnr;
            if (gn < N) {
                long long r0 = (long long)(k0p + bkh * 4) * ldbp + gn;
                pbh.x = Bbh[r0];
                pbh.y = Bbh[r0 + ldbp];
                pbh.z = Bbh[r0 + 2 * ldbp];
                pbh.w = Bbh[r0 + 3 * ldbp];
                pbl.x = Bbl[r0];
                pbl.y = Bbl[r0 + ldbp];
                pbl.z = Bbl[r0 + 2 * ldbp];
                pbl.w = Bbl[r0 + 3 * ldbp];
            } else {
                pbh = make_uint4(0, 0, 0, 0);
                pbl = pbh;
            }
        }
        pbh.x ^= msk; pbh.y ^= msk; pbh.z ^= msk; pbh.w ^= msk;
        pbl.x ^= msk; pbl.y ^= msk; pbl.z ^= msk; pbl.w ^= msk;
    };
    auto stAB = [&](int buf) {
        *(uint4*)&As[buf][0][a_soff] = pah;
        *(uint4*)&As[buf][1][a_soff] = pal;
        if (TB) {
            *(uint4*)&Bs[buf][0][a_soff] = pbh;
            *(uint4*)&Bs[buf][1][a_soff] = pbl;
        } else {
            *(uint4*)&Bs[buf][0][b_soff] = pbh;
            *(uint4*)&Bs[buf][1][b_soff] = pbl;
        }
    };
    auto compute = [&](int buf) {
        unsigned bufA = asb + buf * 8192;
        unsigned bufB = bsb + buf * 8192;
        unsigned bh[4][2], bl[4][2];
#pragma unroll
        for (int p = 0; p < 2; p++) {
            unsigned r[4];
            ldm4(r, bufB + b_frag + p * 512);
            bh[2 * p][0] = r[0]; bh[2 * p + 1][0] = r[1];
            bh[2 * p][1] = r[2]; bh[2 * p + 1][1] = r[3];
            ldm4(r, bufB + 4096 + b_frag + p * 512);
            bl[2 * p][0] = r[0]; bl[2 * p + 1][0] = r[1];
            bl[2 * p][1] = r[2]; bl[2 * p + 1][1] = r[3];
        }
#pragma unroll
        for (int mt = 0; mt < 4; mt++) {
            unsigned ah[4], al[4];
            ldm4(ah, bufA + a_frag + mt * 512);
            ldm4(al, bufA + 4096 + a_frag + mt * 512);
#pragma unroll
            for (int nt = 0; nt < 4; nt++) {
                mma_bf16(acc[mt][nt], ah, bh[nt]);
                mma_bf16(acc[mt][nt], al, bh[nt]);
                mma_bf16(acc[mt][nt], ah, bl[nt]);
            }
        }
    };

    ld(0);
    stAB(0);
    __syncthreads();
    for (int t = 0; t < ntot; t++) {
        if (t + 1 < ntot) ld(t + 1);
        compute(t & 1);
        if (t + 1 < ntot) stAB((t + 1) & 1);
        __syncthreads();
    }

    const int ldcP = ldc >> 1;
#pragma unroll
    for (int mt = 0; mt < 4; mt++) {
        int m0 = brow + wr * 64 + mt * 16 + gr;
#pragma unroll
        for (int nt = 0; nt < 4; nt++) {
            int n0 = bcol + wc * 32 + nt * 8 + gc * 2;
            if (n0 >= N) continue;
            const float* c = acc[mt][nt];
            float b0 = 0.f, b1v = 0.f;
            if (biasz) {
                b0 = biasz[n0];
                b1v = biasz[n0 + 1];
            }
            float v0 = alpha * c[0] + b0, v1 = alpha * c[1] + b1v;
            float v2 = alpha * c[2] + b0, v3 = alpha * c[3] + b1v;
            if (dorelu) {
                v0 = fmaxf(v0, 0.f); v1 = fmaxf(v1, 0.f);
                v2 = fmaxf(v2, 0.f); v3 = fmaxf(v3, 0.f);
            }
            if (Cfb) {
                long long off = (long long)m0 * ldc + n0;
                float2 o;
                if (beta != 0.f) {
                    o = *(const float2*)&Cfb[off];
                    v0 += beta * o.x; v1 += beta * o.y;
                }
                *(float2*)&Cfb[off] = make_float2(v0, v1);
                off += (long long)8 * ldc;
                if (beta != 0.f) {
                    o = *(const float2*)&Cfb[off];
                    v2 += beta * o.x; v3 += beta * o.y;
                }
                *(float2*)&Cfb[off] = make_float2(v2, v3);
            }
            if (Chb) {
                unsigned h, l;
                long long off = (long long)m0 * ldcP + (n0 >> 1);
                split2(v0, v1, h, l);
                Chb[off] = h; Clb[off] = l;
                off += (long long)8 * ldcP;
                split2(v2, v3, h, l);
                Chb[off] = h; Clb[off] = l;
            }
        }
    }
}

// ---------------- split-K projection (fp32 in, in-loop split; small) ----------
__global__ void __launch_bounds__(256, 2) proj_splitk_tc(
    const float* __restrict__ pk, const float* __restrict__ pv,
    const float* __restrict__ KV, float* __restrict__ P) {
    __shared__ unsigned As[2][2][8 * 136];
    __shared__ unsigned Bs[2][2][8 * 136];
    const int z = blockIdx.z;
    const int p = z >> 5;
    const int s = z & 31;
    const float* A = (p < 2) ? pk : pv;
    const float* B = KV + (long long)p * ND;
    const int chunk = N_TOK / NSPLIT;
    const int kbeg = s * chunk;
    const int brow = blockIdx.y * 128, bcol = blockIdx.x * 128;
    const int tid = threadIdx.x;
    const int lane = tid & 31, w = tid >> 5;
    const int wr = w >> 2, wc = w & 3;
    const int gr = lane >> 2, gc = lane & 3;
    const int kp = tid >> 5;
    const int an = lane * 4;

    float acc[4][4][4];
#pragma unroll
    for (int i = 0; i < 4; i++)
#pragma unroll
        for (int j = 0; j < 4; j++)
#pragma unroll
            for (int q = 0; q < 4; q++) acc[i][j][q] = 0.f;

    float4 pa0, pa1, pb0, pb1;
    auto ld = [&](int k0) {
        pa0 = *(const float4*)&A[(long long)(k0 + 2 * kp) * K_LR + brow + an];
        pa1 = *(const float4*)&A[(long long)(k0 + 2 * kp + 1) * K_LR + brow + an];
        pb0 = *(const float4*)&B[(long long)(k0 + 2 * kp) * D_MODEL + bcol + an];
        pb1 = *(const float4*)&B[(long long)(k0 + 2 * kp + 1) * D_MODEL + bcol + an];
    };
    auto st = [&](int buf) {
        unsigned h, l;
        unsigned base = kp * 136 + an;
        split2(pa0.x, pa1.x, h, l); As[buf][0][base + 0] = h; As[buf][1][base + 0] = l;
        split2(pa0.y, pa1.y, h, l); As[buf][0][base + 1] = h; As[buf][1][base + 1] = l;
        split2(pa0.z, pa1.z, h, l); As[buf][0][base + 2] = h; As[buf][1][base + 2] = l;
        split2(pa0.w, pa1.w, h, l); As[buf][0][base + 3] = h; As[buf][1][base + 3] = l;
        split2(pb0.x, pb1.x, h, l); Bs[buf][0][base + 0] = h; Bs[buf][1][base + 0] = l;
        split2(pb0.y, pb1.y, h, l); Bs[buf][0][base + 1] = h; Bs[buf][1][base + 1] = l;
        split2(pb0.z, pb1.z, h, l); Bs[buf][0][base + 2] = h; Bs[buf][1][base + 2] = l;
        split2(pb0.w, pb1.w, h, l); Bs[buf][0][base + 3] = h; Bs[buf][1][base + 3] = l;
    };
    auto compute = [&](int buf) {
        unsigned bh[4][2], bl[4][2];
#pragma unroll
        for (int nt = 0; nt < 4; nt++) {
            int n = wc * 32 + nt * 8 + gr;
            bh[nt][0] = Bs[buf][0][gc * 136 + n];
            bh[nt][1] = Bs[buf][0][(gc + 4) * 136 + n];
            bl[nt][0] = Bs[buf][1][gc * 136 + n];
            bl[nt][1] = Bs[buf][1][(gc + 4) * 136 + n];
        }
#pragma unroll
        for (int mt = 0; mt < 4; mt++) {
            int m = wr * 64 + mt * 16;
            unsigned ah[4], al[4];
            ah[0] = As[buf][0][gc * 136 + m + gr];
            ah[1] = As[buf][0][gc * 136 + m + 8 + gr];
            ah[2] = As[buf][0][(gc + 4) * 136 + m + gr];
            ah[3] = As[buf][0][(gc + 4) * 136 + m + 8 + gr];
            al[0] = As[buf][1][gc * 136 + m + gr];
            al[1] = As[buf][1][gc * 136 + m + 8 + gr];
            al[2] = As[buf][1][(gc + 4) * 136 + m + gr];
            al[3] = As[buf][1][(gc + 4) * 136 + m + 8 + gr];
#pragma unroll
            for (int nt = 0; nt < 4; nt++) {
                mma_bf16(acc[mt][nt], ah, bh[nt]);
                mma_bf16(acc[mt][nt], al, bh[nt]);
                mma_bf16(acc[mt][nt], ah, bl[nt]);
            }
        }
    };

    ld(kbeg);
    st(0);
    __syncthreads();
    const int ntile = chunk / KT;
    for (int t = 0; t < ntile; t++) {
        if (t + 1 < ntile) ld(kbeg + (t + 1) * KT);
        compute(t & 1);
        if (t + 1 < ntile) st((t + 1) & 1);
        __syncthreads();
    }

    float* Pz = P + (long long)z * KD;
#pragma unroll
    for (int mt = 0; mt < 4; mt++) {
        int m0 = brow + wr * 64 + mt * 16 + gr;
#pragma unroll
        for (int nt = 0; nt < 4; nt++) {
            int n0 = bcol + wc * 32 + nt * 8 + gc * 2;
            const float* c = acc[mt][nt];
            *(float2*)&Pz[(long long)m0 * D_MODEL + n0] = make_float2(c[0], c[1]);
            *(float2*)&Pz[(long long)(m0 + 8) * D_MODEL + n0] = make_float2(c[2], c[3]);
        }
    }
}

// reduce split-K partials and emit split KP (TB layout) / VP (nonTB layout)
__global__ void proj_reduce_sp(const float* __restrict__ P,
                               unsigned* __restrict__ KP, unsigned* __restrict__ VP) {
    const int half = (int)KDH;
    int i = blockIdx.x * blockDim.x + threadIdx.x;
    if (i >= 4 * half) return;
    int p = i / half, j = i % half;
    long long e0, e1;
    if (p < 2) {
        int row = j / (D_MODEL / 2), c = j % (D_MODEL / 2);
        e0 = (long long)row * D_MODEL + 2 * c;
        e1 = e0 + 1;
    } else {
        int n = j % D_MODEL, kp2 = j / D_MODEL;
        e0 = (long long)(2 * kp2) * D_MODEL + n;
        e1 = e0 + D_MODEL;
    }
    const float* base = P + (long long)p * NSPLIT * KD;
    float s0 = 0.f, s1 = 0.f;
#pragma unroll 8
    for (int s = 0; s < NSPLIT; s++) {
        s0 += base[(long long)s * KD + e0];
        s1 += base[(long long)s * KD + e1];
    }
    unsigned h, l;
    split2(s0, s1, h, l);
    if (p < 2) {
        KP[(long long)p * 2 * half + j] = h;
        KP[(long long)p * 2 * half + half + j] = l;
    } else {
        int q = p - 2;
        VP[(long long)q * 2 * half + j] = h;
        VP[(long long)q * 2 * half + half + j] = l;
    }
}

// fp32 [2*Kd][N] (both depths) -> packed hi/lo [halfK][N]
__global__ void conv_nonTB(const float* __restrict__ W, unsigned* __restrict__ Wh,
                           unsigned* __restrict__ Wl, long long halfK, int N) {
    long long i = (long long)blockIdx.x * blockDim.x + threadIdx.x;
    long long total = halfK * N;
    if (i >= total) return;
    int n = (int)(i % N);
    long long kp = i / N;
    unsigned h, l;
    split2(W[(2 * kp) * N + n], W[(2 * kp + 1) * N + n], h, l);
    Wh[i] = h;
    Wl[i] = l;
}

// ---------------- host launcher ----------------
static inline void gemmSP(bool tb,
                          const unsigned* A1h, const unsigned* A1l,
                          const unsigned* A2h, const unsigned* A2l,
                          const unsigned* B1h, const unsigned* B1l,
                          const unsigned* B2h, const unsigned* B2l,
                          float* Cf, unsigned* Ch, unsigned* Cl,
                          const float* b1, const float* b2,
                          int M, int N, int Kd, int ldap, int ldbp, int ldc,
                          long long sAp, long long sBp, long long sC, long long sCp,
                          int nbatch, int nzc, float alpha, float beta, int relu) {
    dim3 grid((N + 127) / 128, (M + 127) / 128, nbatch * nzc);
    if (tb)
        gemm_sp<true><<<grid, 256>>>(A1h, A1l, A2h, A2l, B1h, B1l, B2h, B2l, Cf, Ch, Cl, b1, b2,
                                     M, N, Kd, ldap, ldbp, ldc, sAp, sBp, sC, sCp, alpha, beta, nzc, relu);
    else
        gemm_sp<false><<<grid, 256>>>(A1h, A1l, A2h, A2l, B1h, B1l, B2h, B2l, Cf, Ch, Cl, b1, b2,
                                      M, N, Kd, ldap, ldbp, ldc, sAp, sBp, sC, sCp, alpha, beta, nzc, relu);
}

extern "C" void kernel_launch(void* const* d_in, const int* in_sizes, int n_in,
                              void* d_out, int out_size) {
    const float* x_real = (const float*)d_in[0];
    const float* x_imag = (const float*)d_in[1];
    const float* Wq = (const float*)d_in[2];
    const float* bq = (const float*)d_in[3];
    const float* Wk = (const float*)d_in[4];
    const float* bk = (const float*)d_in[5];
    const float* Wv = (const float*)d_in[6];
    const float* bv = (const float*)d_in[7];
    const float* pk = (const float*)d_in[8];
    const float* pv = (const float*)d_in[9];
    const float* Wout = (const float*)d_in[10];
    const float* bout = (const float*)d_in[11];
    const float* W1r = (const float*)d_in[12];
    const float* W1i = (const float*)d_in[13];
    const float* b1r = (const float*)d_in[14];
    const float* b1i = (const float*)d_in[15];
    const float* W2r = (const float*)d_in[16];
    const float* W2i = (const float*)d_in[17];
    const float* b2r = (const float*)d_in[18];
    const float* b2i = (const float*)d_in[19];

    float* xr = (float*)d_out;
    float* xi = xr + ND;

    unsigned *Nsp, *Qsp, *KPsp, *VPsp, *Dsp, *Osp, *Hsp;
    unsigned *sWq, *sWk, *sWv, *sWo, *sW1r, *sW1i, *sW2r, *sW2i;
    float *KVf, *PSUM;
    cudaGetSymbolAddress((void**)&Nsp, g_Nsp);
    cudaGetSymbolAddress((void**)&Qsp, g_Qsp);
    cudaGetSymbolAddress((void**)&KPsp, g_KPsp);
    cudaGetSymbolAddress((void**)&VPsp, g_VPsp);
    cudaGetSymbolAddress((void**)&Dsp, g_Dsp);
    cudaGetSymbolAddress((void**)&Osp, g_Osp);
    cudaGetSymbolAddress((void**)&Hsp, g_Hsp);
    cudaGetSymbolAddress((void**)&KVf, g_KVf);
    cudaGetSymbolAddress((void**)&PSUM, g_PSUM);
    cudaGetSymbolAddress((void**)&sWq, g_Wq);
    cudaGetSymbolAddress((void**)&sWk, g_Wk);
    cudaGetSymbolAddress((void**)&sWv, g_Wv);
    cudaGetSymbolAddress((void**)&sWo, g_Wo);
    cudaGetSymbolAddress((void**)&sW1r, g_W1r);
    cudaGetSymbolAddress((void**)&sW1i, g_W1i);
    cudaGetSymbolAddress((void**)&sW2r, g_W2r);
    cudaGetSymbolAddress((void**)&sW2i, g_W2i);

    cudaMemcpyAsync(xr, x_real, ND * sizeof(float), cudaMemcpyDeviceToDevice, 0);
    cudaMemcpyAsync(xi, x_imag, ND * sizeof(float), cudaMemcpyDeviceToDevice, 0);

    // ---- pre-split all weights (both depths at once; rows pair within depth)
    {
        long long hq = 2LL * 256;  // 2 depths * (512/2)
        conv_nonTB<<<(int)((hq * 512 + 255) / 256), 256>>>(Wq, sWq, sWq + 2 * 131072LL, hq, 512);
        conv_nonTB<<<(int)((hq * 512 + 255) / 256), 256>>>(Wk, sWk, sWk + 2 * 131072LL, hq, 512);
        conv_nonTB<<<(int)((hq * 512 + 255) / 256), 256>>>(Wv, sWv, sWv + 2 * 131072LL, hq, 512);
        conv_nonTB<<<(int)((hq * 512 + 255) / 256), 256>>>(Wout, sWo, sWo + 2 * 131072LL, hq, 512);
        long long h1 = 2LL * 256;
        conv_nonTB<<<(int)((h1 * 2048 + 255) / 256), 256>>>(W1r, sW1r, sW1r + 2 * 524288LL, h1, 2048);
        conv_nonTB<<<(int)((h1 * 2048 + 255) / 256), 256>>>(W1i, sW1i, sW1i + 2 * 524288LL, h1, 2048);
        long long h2 = 2LL * 1024;
        conv_nonTB<<<(int)((h2 * 512 + 255) / 256), 256>>>(W2r, sW2r, sW2r + 2 * 524288LL, h2, 512);
        conv_nonTB<<<(int)((h2 * 512 + 255) / 256), 256>>>(W2i, sW2i, sW2i + 2 * 524288LL, h2, 512);
    }
    // NOTE: split-weight layout after conv: hi covers both depths contiguously at
    // offset 0, lo at +2*perdepth. Per-depth offset within hi/lo = d*perdepth.

    for (int d = 0; d < 2; d++) {
        const long long oq = (long long)d * 131072;   // per-depth offset (qkvo)
        const long long o1 = (long long)d * 524288;   // W1
        const long long o2 = (long long)d * 524288;   // W2
        const float* bq_d = bq + (size_t)d * D_MODEL;
        const float* bk_d = bk + (size_t)d * D_MODEL;
        const float* bv_d = bv + (size_t)d * D_MODEL;
        const float* pk_d = pk + (size_t)d * N_TOK * K_LR;
        const float* pv_d = pv + (size_t)d * N_TOK * K_LR;
        const float* bo_d = bout + (size_t)d * D_MODEL;
        const float* b1r_d = b1r + (size_t)d * D_FF;
        const float* b1i_d = b1i + (size_t)d * D_FF;
        const float* b2r_d = b2r + (size_t)d * D_MODEL;
        const float* b2i_d = b2i + (size_t)d * D_MODEL;

        // ---- LN1 -> Nsp (split)
        cln_kernel<<<N_TOK, 512>>>(xr, xi, Nsp);

        // ---- QKV: Q -> split; K,V -> fp32 (for proj). z=2 over r/i.
        gemmSP(false, Nsp, Nsp + NDH, nullptr, nullptr,
               sWq + oq, sWq + 2 * 131072LL + oq, nullptr, nullptr,
               nullptr, Qsp, Qsp + NDH, bq_d, nullptr,
               N_TOK, D_MODEL, D_MODEL, 256, 512, 512,
               2 * NDH, 0, 2 * NDH, 0, 2, 1, 1.f, 0.f, 0);
        gemmSP(false, Nsp, Nsp + NDH, nullptr, nullptr,
               sWk + oq, sWk + 2 * 131072LL + oq, nullptr, nullptr,
               KVf, nullptr, nullptr, bk_d, nullptr,
               N_TOK, D_MODEL, D_MODEL, 256, 512, 512,
               2 * NDH, 0, ND, 0, 2, 1, 1.f, 0.f, 0);
        gemmSP(false, Nsp, Nsp + NDH, nullptr, nullptr,
               sWv + oq, sWv + 2 * 131072LL + oq, nullptr, nullptr,
               KVf + 2 * ND, nullptr, nullptr, bv_d, nullptr,
               N_TOK, D_MODEL, D_MODEL, 256, 512, 512,
               2 * NDH, 0, ND, 0, 2, 1, 1.f, 0.f, 0);

        // ---- low-rank projections -> split KP/VP
        {
            dim3 g(D_MODEL / 128, K_LR / 128, 4 * NSPLIT);
            proj_splitk_tc<<<g, 256>>>(pk_d, pv_d, KVf, PSUM);
            proj_reduce_sp<<<(int)((4 * KDH + 255) / 256), 256>>>(PSUM, KPsp, VPsp);
        }

        // ---- complex dots -> Dsp (split). z = 8 heads x 2 parts.
        gemmSP(true, Qsp, Qsp + NDH, Qsp + 2 * NDH, Qsp + 3 * NDH,
               KPsp, KPsp + KDH, KPsp + 2 * KDH, KPsp + 3 * KDH,
               nullptr, Dsp, Dsp + HNKH, nullptr, nullptr,
               N_TOK, K_LR, DHEAD, 256, 256, 256,
               32, 32, NKH, 2 * HNKH, H_HEADS, 2, ATTN_SCALE, 0.f, 0);

        // ---- complex attn out -> Osp (split). z = 8 heads x 2 parts.
        gemmSP(false, Dsp, Dsp + HNKH, Dsp + 2 * HNKH, Dsp + 3 * HNKH,
               VPsp, VPsp + KDH, VPsp + 2 * KDH, VPsp + 3 * KDH,
               nullptr, Osp, Osp + NDH, nullptr, nullptr,
               N_TOK, DHEAD, K_LR, 128, 512, 512,
               NKH, 64, 32, 2 * NDH, H_HEADS, 2, 1.f, 0.f, 0);

        // ---- output projection + residual (fp32). z=2 over r/i.
        gemmSP(false, Osp, Osp + NDH, nullptr, nullptr,
               sWo + oq, sWo + 2 * 131072LL + oq, nullptr, nullptr,
               xr, nullptr, nullptr, bo_d, nullptr,
               N_TOK, D_MODEL, D_MODEL, 256, 512, 512,
               2 * NDH, 0, ND, 0, 2, 1, 1.f, 1.f, 0);

        // ---- LN2 -> Nsp
        cln_kernel<<<N_TOK, 512>>>(xr, xi, Nsp);

        // ---- FFN1 (+relu) -> Hsp (split). z = 2 parts, chained complex.
        gemmSP(false, Nsp, Nsp + NDH, Nsp + 2 * NDH, Nsp + 3 * NDH,
               sW1r + o1, sW1r + 2 * 524288LL + o1, sW1i + o1, sW1i + 2 * 524288LL + o1,
               nullptr, Hsp, Hsp + NFFH, b1r_d, b1i_d,
               N_TOK, D_FF, D_MODEL, 256, 2048, 2048,
               0, 0, 0, 2 * NFFH, 1, 2, 1.f, 0.f, 1);

        // ---- FFN2 + residual (fp32). z = 2 parts, chained complex.
        gemmSP(false, Hsp, Hsp + NFFH, Hsp + 2 * NFFH, Hsp + 3 * NFFH,
               sW2r + o2, sW2r + 2 * 524288LL + o2, sW2i + o2, sW2i + 2 * 524288LL + o2,
               xr, nullptr, nullptr, b2r_d, b2i_d,
               N_TOK, D_MODEL, D_FF, 1024, 512, 512,
               0, 0, 0, ND, 1, 2, 1.f, 1.f, 0);
    }
}

// round 8
// speedup vs baseline: 3.0834x; 1.0153x over previous
#include <cuda_runtime.h>
#include <cstdint>

#define N_TOK 4096
#define D_MODEL 512
#define K_LR 256
#define H_HEADS 8
#define DHEAD 64
#define D_FF 2048
#define EPS_LN 1e-5f
#define ATTN_SCALE 0.125f
#define NSPLIT 32
#define KT 16

#define ND ((long long)N_TOK * D_MODEL)
#define KD ((long long)K_LR * D_MODEL)
#define NK ((long long)N_TOK * K_LR)
#define HNK ((long long)H_HEADS * NK)
#define NFF ((long long)N_TOK * D_FF)

#define NDH 1048576LL
#define KDH 65536LL
#define NKH 524288LL
#define HNKH 4194304LL
#define NFFH 4194304LL

// ---------------- scratch ----------------
__device__ unsigned g_Nsp[4 * NDH];
__device__ unsigned g_Qsp[4 * NDH];
__device__ float    g_KVf[4 * ND];
__device__ unsigned g_KPsp[6 * KDH];   // rh,rl,ih,il,inh,inl
__device__ unsigned g_VPsp[6 * KDH];   // TB layout [D_MODEL][K_LR/2]
__device__ unsigned g_Dsp[4 * HNKH];
__device__ unsigned g_Osp[4 * NDH];
__device__ unsigned g_Hsp[4 * NFFH];
__device__ float    g_PSUM[4 * NSPLIT * KD];
// TB split weights. Block stride = 2 depths * perdepth(u32).
// QKV/O perdepth = 131072 -> blocks of 262144. FFN perdepth = 524288 -> blocks of 1048576.
__device__ unsigned g_Wq[2 * 262144];
__device__ unsigned g_Wk[2 * 262144];
__device__ unsigned g_Wv[2 * 262144];
__device__ unsigned g_Wo[2 * 262144];
__device__ unsigned g_W1r[2 * 1048576];
__device__ unsigned g_W1i[4 * 1048576];
__device__ unsigned g_W2r[2 * 1048576];
__device__ unsigned g_W2i[4 * 1048576];

// ---------------- helpers ----------------
__device__ __forceinline__ unsigned packbf(float x0, float x1) {
    unsigned r;
    asm("cvt.rn.bf16x2.f32 %0, %1, %2;" : "=r"(r) : "f"(x1), "f"(x0));
    return r;
}
__device__ __forceinline__ void split2(float x0, float x1, unsigned& hi, unsigned& lo) {
    hi = packbf(x0, x1);
    float h0 = __uint_as_float(hi << 16);
    float h1 = __uint_as_float(hi & 0xffff0000u);
    lo = packbf(x0 - h0, x1 - h1);
}
__device__ __forceinline__ void mma_bf16(float* c, const unsigned* a, const unsigned* b) {
    asm volatile(
        "mma.sync.aligned.m16n8k16.row.col.f32.bf16.bf16.f32 "
        "{%0,%1,%2,%3}, {%4,%5,%6,%7}, {%8,%9}, {%0,%1,%2,%3};\n"
        : "+f"(c[0]), "+f"(c[1]), "+f"(c[2]), "+f"(c[3])
        : "r"(a[0]), "r"(a[1]), "r"(a[2]), "r"(a[3]), "r"(b[0]), "r"(b[1]));
}
__device__ __forceinline__ void ldm4(unsigned* r, unsigned addr) {
    asm volatile(
        "ldmatrix.sync.aligned.m8n8.x4.shared.b16 {%0,%1,%2,%3}, [%4];"
        : "=r"(r[0]), "=r"(r[1]), "=r"(r[2]), "=r"(r[3])
        : "r"(addr));
}
__device__ __forceinline__ void cpasync16(unsigned dst, const void* src, int srcsize) {
    asm volatile("cp.async.cg.shared.global [%0], [%1], 16, %2;"
                 :: "r"(dst), "l"(src), "r"(srcsize) : "memory");
}
#define CP_COMMIT() asm volatile("cp.async.commit_group;" ::: "memory")
#define CP_WAIT1() asm volatile("cp.async.wait_group 1;" ::: "memory")

// ---------------- block reduction ----------------
__device__ __forceinline__ float blockSum(float v, float* red) {
#pragma unroll
    for (int o = 16; o > 0; o >>= 1) v += __shfl_xor_sync(0xffffffffu, v, o);
    int lane = threadIdx.x & 31, w = threadIdx.x >> 5;
    if (lane == 0) red[w] = v;
    __syncthreads();
    if (w == 0) {
        float x = (lane < 16) ? red[lane] : 0.f;
#pragma unroll
        for (int o = 8; o > 0; o >>= 1) x += __shfl_xor_sync(0xffffffffu, x, o);
        if (lane == 0) red[0] = x;
    }
    __syncthreads();
    float r = red[0];
    __syncthreads();
    return r;
}

// ---------------- complex layernorm -> split bf16 ----------------
__global__ void cln_kernel(const float* __restrict__ xr, const float* __restrict__ xi,
                           unsigned* __restrict__ Nsp) {
    __shared__ float red[16];
    int row = blockIdx.x;
    int t = threadIdx.x;
    long long base = (long long)row * D_MODEL;
    float vr = xr[base + t];
    float vi = xi[base + t];
    const float invD = 1.0f / D_MODEL;
    float mr = blockSum(vr, red) * invD;
    float mi = blockSum(vi, red) * invD;
    float cr = vr - mr, ci = vi - mi;
    float Crr = blockSum(cr * cr, red) * invD + EPS_LN;
    float Cii = blockSum(ci * ci, red) * invD + EPS_LN;
    float Cri = blockSum(cr * ci, red) * invD;
    float s = sqrtf(Crr * Cii - Cri * Cri);
    float tt = sqrtf(Cii + Crr + 2.0f * s);
    float inv = 1.0f / (s * tt);
    float Rrr = (Cii + s) * inv;
    float Rii = (Crr + s) * inv;
    float Rri = -Cri * inv;
    float outr = Rrr * cr + Rri * ci;
    float outi = Rii * ci + Rri * cr;
    float outr2 = __shfl_down_sync(0xffffffffu, outr, 1);
    float outi2 = __shfl_down_sync(0xffffffffu, outi, 1);
    if ((t & 1) == 0) {
        long long o = (long long)row * (D_MODEL / 2) + (t >> 1);
        unsigned h, l;
        split2(outr, outr2, h, l);
        Nsp[o] = h;
        Nsp[NDH + o] = l;
        split2(outi, outi2, h, l);
        Nsp[2 * NDH + o] = h;
        Nsp[3 * NDH + o] = l;
    }
}

// ---------------- cp.async 3-stage TB GEMM (all operands pre-split TB) -------
__global__ void __launch_bounds__(256, 2) gemm_sp(
    const unsigned* __restrict__ A1h, const unsigned* __restrict__ A1l,
    const unsigned* __restrict__ A2h, const unsigned* __restrict__ A2l,
    const unsigned* __restrict__ B1h, const unsigned* __restrict__ B1l,
    const unsigned* __restrict__ B2h, const unsigned* __restrict__ B2l,
    const unsigned* __restrict__ B2nh, const unsigned* __restrict__ B2nl,
    float* __restrict__ Cf, unsigned* __restrict__ Ch, unsigned* __restrict__ Cl,
    const float* __restrict__ bias1, const float* __restrict__ bias2,
    int M, int N, int Kd, int ldap, int ldbp, int ldc,
    long long sAp, long long sBp, long long sC, long long sCp,
    float alpha, float beta, int nzc, int dorelu) {
    __shared__ unsigned smem[3 * 4096];

    const int z = blockIdx.z;
    const int part = (nzc == 2) ? (z & 1) : 0;
    const int bz = (nzc == 2) ? (z >> 1) : z;

    const unsigned* Ac0h = A1h + bz * sAp;
    const unsigned* Ac0l = A1l + bz * sAp;
    const unsigned* Ac1h = A2h ? A2h + bz * sAp : nullptr;
    const unsigned* Ac1l = A2h ? A2l + bz * sAp : nullptr;
    const unsigned *Bc0h, *Bc0l, *Bc1h = nullptr, *Bc1l = nullptr;
    const float* biasz;
    if (part == 0) {
        Bc0h = B1h + bz * sBp;
        Bc0l = B1l + bz * sBp;
        if (A2h) {
            Bc1h = B2nh + bz * sBp;
            Bc1l = B2nl + bz * sBp;
        }
        biasz = bias1;
    } else {
        Bc0h = B2h + bz * sBp;
        Bc0l = B2l + bz * sBp;
        Bc1h = B1h + bz * sBp;
        Bc1l = B1l + bz * sBp;
        biasz = bias2;
    }
    float* Cfb = Cf ? Cf + bz * sC + (long long)part * sCp : nullptr;
    unsigned* Chb = Ch ? Ch + bz * sC + (long long)part * sCp : nullptr;
    unsigned* Clb = Ch ? Cl + bz * sC + (long long)part * sCp : nullptr;

    const int brow = blockIdx.y * 128, bcol = blockIdx.x * 128;
    const int tid = threadIdx.x;
    const int lane = tid & 31, w = tid >> 5;
    const int wr = w >> 2, wc = w & 3;
    const int gr = lane >> 2, gc = lane & 3;

    float acc[4][4][4];
#pragma unroll
    for (int i = 0; i < 4; i++)
#pragma unroll
        for (int j = 0; j < 4; j++)
#pragma unroll
            for (int q = 0; q < 4; q++) acc[i][j][q] = 0.f;

    const int am = tid >> 1, kh = tid & 1;
    const unsigned a_idx = am * 8 + ((kh ^ ((am >> 2) & 1)) * 4);

    const int lm_row = ((lane >> 3) & 1) * 8 + (lane & 7);
    const int lm_g = lane >> 4;
    const int a_mb = wr * 64 + lm_row;
    const unsigned a_frag = (a_mb * 8 + ((lm_g ^ ((a_mb >> 2) & 1)) * 4)) * 4;
    const int b_nb = wc * 32 + lm_row;
    const unsigned b_frag = (b_nb * 8 + ((lm_g ^ ((b_nb >> 2) & 1)) * 4)) * 4;

    const unsigned sbase = (unsigned)__cvta_generic_to_shared(&smem[0]);

    const int ntile1 = Kd / KT;
    const int ntot = (A2h ? 2 : 1) * ntile1;
    const int gn = bcol + am;
    const int bok = (gn < N) ? 16 : 0;
    const int gnc = bok ? gn : 0;

    auto ldst = [&](int t, int stage) {
        int ch = (t >= ntile1);
        const unsigned* Ah = ch ? Ac1h : Ac0h;
        const unsigned* Al = ch ? Ac1l : Ac0l;
        const unsigned* Bh = ch ? Bc1h : Bc0h;
        const unsigned* Bl = ch ? Bc1l : Bc0l;
        int k0p = (ch ? t - ntile1 : t) * 8;
        unsigned sa = sbase + stage * 16384 + a_idx * 4;
        long long aoff = (long long)(brow + am) * ldap + k0p + kh * 4;
        cpasync16(sa, Ah + aoff, 16);
        cpasync16(sa + 4096, Al + aoff, 16);
        long long boff = (long long)gnc * ldbp + k0p + kh * 4;
        cpasync16(sa + 8192, Bh + boff, bok);
        cpasync16(sa + 12288, Bl + boff, bok);
    };
    auto compute = [&](int stage) {
        unsigned bufA = sbase + stage * 16384;
        unsigned bufB = bufA + 8192;
        unsigned bh[4][2], bl[4][2];
#pragma unroll
        for (int p = 0; p < 2; p++) {
            unsigned r[4];
            ldm4(r, bufB + b_frag + p * 512);
            bh[2 * p][0] = r[0]; bh[2 * p + 1][0] = r[1];
            bh[2 * p][1] = r[2]; bh[2 * p + 1][1] = r[3];
            ldm4(r, bufB + 4096 + b_frag + p * 512);
            bl[2 * p][0] = r[0]; bl[2 * p + 1][0] = r[1];
            bl[2 * p][1] = r[2]; bl[2 * p + 1][1] = r[3];
        }
#pragma unroll
        for (int mt = 0; mt < 4; mt++) {
            unsigned ah[4], al[4];
            ldm4(ah, bufA + a_frag + mt * 512);
            ldm4(al, bufA + 4096 + a_frag + mt * 512);
#pragma unroll
            for (int nt = 0; nt < 4; nt++) {
                mma_bf16(acc[mt][nt], ah, bh[nt]);
                mma_bf16(acc[mt][nt], al, bh[nt]);
                mma_bf16(acc[mt][nt], ah, bl[nt]);
            }
        }
    };

    ldst(0, 0);
    CP_COMMIT();
    if (ntot > 1) ldst(1, 1);
    CP_COMMIT();
    for (int t = 0; t < ntot; t++) {
        CP_WAIT1();
        __syncthreads();
        if (t + 2 < ntot) ldst(t + 2, (t + 2) % 3);
        CP_COMMIT();
        compute(t % 3);
    }

    const int ldcP = ldc >> 1;
#pragma unroll
    for (int mt = 0; mt < 4; mt++) {
        int m0 = brow + wr * 64 + mt * 16 + gr;
#pragma unroll
        for (int nt = 0; nt < 4; nt++) {
            int n0 = bcol + wc * 32 + nt * 8 + gc * 2;
            if (n0 >= N) continue;
            const float* c = acc[mt][nt];
            float b0 = 0.f, b1v = 0.f;
            if (biasz) {
                b0 = biasz[n0];
                b1v = biasz[n0 + 1];
            }
            float v0 = alpha * c[0] + b0, v1 = alpha * c[1] + b1v;
            float v2 = alpha * c[2] + b0, v3 = alpha * c[3] + b1v;
            if (dorelu) {
                v0 = fmaxf(v0, 0.f); v1 = fmaxf(v1, 0.f);
                v2 = fmaxf(v2, 0.f); v3 = fmaxf(v3, 0.f);
            }
            if (Cfb) {
                long long off = (long long)m0 * ldc + n0;
                float2 o;
                if (beta != 0.f) {
                    o = *(const float2*)&Cfb[off];
                    v0 += beta * o.x; v1 += beta * o.y;
                }
                *(float2*)&Cfb[off] = make_float2(v0, v1);
                off += (long long)8 * ldc;
                if (beta != 0.f) {
                    o = *(const float2*)&Cfb[off];
                    v2 += beta * o.x; v3 += beta * o.y;
                }
                *(float2*)&Cfb[off] = make_float2(v2, v3);
            }
            if (Chb) {
                unsigned h, l;
                long long off = (long long)m0 * ldcP + (n0 >> 1);
                split2(v0, v1, h, l);
                Chb[off] = h; Clb[off] = l;
                off += (long long)8 * ldcP;
                split2(v2, v3, h, l);
                Chb[off] = h; Clb[off] = l;
            }
        }
    }
}

// ---------------- split-K projection ----------
__global__ void __launch_bounds__(256, 2) proj_splitk_tc(
    const float* __restrict__ pk, const float* __restrict__ pv,
    const float* __restrict__ KV, float* __restrict__ P) {
    __shared__ unsigned As[2][2][8 * 136];
    __shared__ unsigned Bs[2][2][8 * 136];
    const int z = blockIdx.z;
    const int p = z >> 5;
    const int s = z & 31;
    const float* A = (p < 2) ? pk : pv;
    const float* B = KV + (long long)p * ND;
    const int chunk = N_TOK / NSPLIT;
    const int kbeg = s * chunk;
    const int brow = blockIdx.y * 128, bcol = blockIdx.x * 128;
    const int tid = threadIdx.x;
    const int lane = tid & 31, w = tid >> 5;
    const int wr = w >> 2, wc = w & 3;
    const int gr = lane >> 2, gc = lane & 3;
    const int kp = tid >> 5;
    const int an = lane * 4;

    float acc[4][4][4];
#pragma unroll
    for (int i = 0; i < 4; i++)
#pragma unroll
        for (int j = 0; j < 4; j++)
#pragma unroll
            for (int q = 0; q < 4; q++) acc[i][j][q] = 0.f;

    float4 pa0, pa1, pb0, pb1;
    auto ld = [&](int k0) {
        pa0 = *(const float4*)&A[(long long)(k0 + 2 * kp) * K_LR + brow + an];
        pa1 = *(const float4*)&A[(long long)(k0 + 2 * kp + 1) * K_LR + brow + an];
        pb0 = *(const float4*)&B[(long long)(k0 + 2 * kp) * D_MODEL + bcol + an];
        pb1 = *(const float4*)&B[(long long)(k0 + 2 * kp + 1) * D_MODEL + bcol + an];
    };
    auto st = [&](int buf) {
        unsigned h, l;
        unsigned base = kp * 136 + an;
        split2(pa0.x, pa1.x, h, l); As[buf][0][base + 0] = h; As[buf][1][base + 0] = l;
        split2(pa0.y, pa1.y, h, l); As[buf][0][base + 1] = h; As[buf][1][base + 1] = l;
        split2(pa0.z, pa1.z, h, l); As[buf][0][base + 2] = h; As[buf][1][base + 2] = l;
        split2(pa0.w, pa1.w, h, l); As[buf][0][base + 3] = h; As[buf][1][base + 3] = l;
        split2(pb0.x, pb1.x, h, l); Bs[buf][0][base + 0] = h; Bs[buf][1][base + 0] = l;
        split2(pb0.y, pb1.y, h, l); Bs[buf][0][base + 1] = h; Bs[buf][1][base + 1] = l;
        split2(pb0.z, pb1.z, h, l); Bs[buf][0][base + 2] = h; Bs[buf][1][base + 2] = l;
        split2(pb0.w, pb1.w, h, l); Bs[buf][0][base + 3] = h; Bs[buf][1][base + 3] = l;
    };
    auto compute = [&](int buf) {
        unsigned bh[4][2], bl[4][2];
#pragma unroll
        for (int nt = 0; nt < 4; nt++) {
            int n = wc * 32 + nt * 8 + gr;
            bh[nt][0] = Bs[buf][0][gc * 136 + n];
            bh[nt][1] = Bs[buf][0][(gc + 4) * 136 + n];
            bl[nt][0] = Bs[buf][1][gc * 136 + n];
            bl[nt][1] = Bs[buf][1][(gc + 4) * 136 + n];
        }
#pragma unroll
        for (int mt = 0; mt < 4; mt++) {
            int m = wr * 64 + mt * 16;
            unsigned ah[4], al[4];
            ah[0] = As[buf][0][gc * 136 + m + gr];
            ah[1] = As[buf][0][gc * 136 + m + 8 + gr];
            ah[2] = As[buf][0][(gc + 4) * 136 + m + gr];
            ah[3] = As[buf][0][(gc + 4) * 136 + m + 8 + gr];
            al[0] = As[buf][1][gc * 136 + m + gr];
            al[1] = As[buf][1][gc * 136 + m + 8 + gr];
            al[2] = As[buf][1][(gc + 4) * 136 + m + gr];
            al[3] = As[buf][1][(gc + 4) * 136 + m + 8 + gr];
#pragma unroll
            for (int nt = 0; nt < 4; nt++) {
                mma_bf16(acc[mt][nt], ah, bh[nt]);
                mma_bf16(acc[mt][nt], al, bh[nt]);
                mma_bf16(acc[mt][nt], ah, bl[nt]);
            }
        }
    };

    ld(kbeg);
    st(0);
    __syncthreads();
    const int ntile = chunk / KT;
    for (int t = 0; t < ntile; t++) {
        if (t + 1 < ntile) ld(kbeg + (t + 1) * KT);
        compute(t & 1);
        if (t + 1 < ntile) st((t + 1) & 1);
        __syncthreads();
    }

    float* Pz = P + (long long)z * KD;
#pragma unroll
    for (int mt = 0; mt < 4; mt++) {
        int m0 = brow + wr * 64 + mt * 16 + gr;
#pragma unroll
        for (int nt = 0; nt < 4; nt++) {
            int n0 = bcol + wc * 32 + nt * 8 + gc * 2;
            const float* c = acc[mt][nt];
            *(float2*)&Pz[(long long)m0 * D_MODEL + n0] = make_float2(c[0], c[1]);
            *(float2*)&Pz[(long long)(m0 + 8) * D_MODEL + n0] = make_float2(c[2], c[3]);
        }
    }
}

// reduce split-K partials; KP: [K_LR][D/2] pairs along D; VP: TB [D][K_LR/2]
__global__ void proj_reduce_sp(const float* __restrict__ P,
                               unsigned* __restrict__ KP, unsigned* __restrict__ VP) {
    const int half = (int)KDH;
    int i = blockIdx.x * blockDim.x + threadIdx.x;
    if (i >= 4 * half) return;
    int p = i / half, j = i % half;
    long long e0, e1;
    if (p < 2) {
        int row = j / (D_MODEL / 2), c = j % (D_MODEL / 2);
        e0 = (long long)row * D_MODEL + 2 * c;
        e1 = e0 + 1;
    } else {
        int dm = j / (K_LR / 2), kp2 = j % (K_LR / 2);
        e0 = (long long)(2 * kp2) * D_MODEL + dm;
        e1 = e0 + D_MODEL;
    }
    const float* base = P + (long long)p * NSPLIT * KD;
    float s0 = 0.f, s1 = 0.f;
#pragma unroll 8
    for (int s = 0; s < NSPLIT; s++) {
        s0 += base[(long long)s * KD + e0];
        s1 += base[(long long)s * KD + e1];
    }
    unsigned h, l;
    split2(s0, s1, h, l);
    unsigned* T = (p < 2) ? KP : VP;
    int q = p & 1;
    T[(long long)(2 * q) * half + j] = h;
    T[(long long)(2 * q + 1) * half + j] = l;
    if (q == 1) {
        T[4LL * half + j] = h ^ 0x80008000u;
        T[5LL * half + j] = l ^ 0x80008000u;
    }
}

// fp32 W [DEPTH][Kd][N] -> TB split [depth][N][Kd/2] (+ optional negated)
__global__ void conv_TB(const float* __restrict__ W, unsigned* __restrict__ Wh,
                        unsigned* __restrict__ Wl, unsigned* __restrict__ Wnh,
                        unsigned* __restrict__ Wnl, int halfK, int N) {
    long long i = (long long)blockIdx.x * blockDim.x + threadIdx.x;
    long long per = (long long)halfK * N;
    if (i >= 2 * per) return;
    int d = (int)(i / per);
    long long r = i % per;
    int n = (int)(r / halfK);
    int kp = (int)(r % halfK);
    long long src = ((long long)d * 2 * halfK + 2 * kp) * N + n;
    unsigned h, l;
    split2(W[src], W[src + N], h, l);
    long long o = (long long)d * per + (long long)n * halfK + kp;
    Wh[o] = h;
    Wl[o] = l;
    if (Wnh) {
        Wnh[o] = h ^ 0x80008000u;
        Wnl[o] = l ^ 0x80008000u;
    }
}

// ---------------- host launcher ----------------
static inline void gemmSP(const unsigned* A1h, const unsigned* A1l,
                          const unsigned* A2h, const unsigned* A2l,
                          const unsigned* B1h, const unsigned* B1l,
                          const unsigned* B2h, const unsigned* B2l,
                          const unsigned* B2nh, const unsigned* B2nl,
                          float* Cf, unsigned* Ch, unsigned* Cl,
                          const float* b1, const float* b2,
                          int M, int N, int Kd, int ldap, int ldbp, int ldc,
                          long long sAp, long long sBp, long long sC, long long sCp,
                          int nbatch, int nzc, float alpha, float beta, int relu) {
    dim3 grid((N + 127) / 128, (M + 127) / 128, nbatch * nzc);
    gemm_sp<<<grid, 256>>>(A1h, A1l, A2h, A2l, B1h, B1l, B2h, B2l, B2nh, B2nl,
                           Cf, Ch, Cl, b1, b2, M, N, Kd, ldap, ldbp, ldc,
                           sAp, sBp, sC, sCp, alpha, beta, nzc, relu);
}

extern "C" void kernel_launch(void* const* d_in, const int* in_sizes, int n_in,
                              void* d_out, int out_size) {
    const float* x_real = (const float*)d_in[0];
    const float* x_imag = (const float*)d_in[1];
    const float* Wq = (const float*)d_in[2];
    const float* bq = (const float*)d_in[3];
    const float* Wk = (const float*)d_in[4];
    const float* bk = (const float*)d_in[5];
    const float* Wv = (const float*)d_in[6];
    const float* bv = (const float*)d_in[7];
    const float* pk = (const float*)d_in[8];
    const float* pv = (const float*)d_in[9];
    const float* Wout = (const float*)d_in[10];
    const float* bout = (const float*)d_in[11];
    const float* W1r = (const float*)d_in[12];
    const float* W1i = (const float*)d_in[13];
    const float* b1r = (const float*)d_in[14];
    const float* b1i = (const float*)d_in[15];
    const float* W2r = (const float*)d_in[16];
    const float* W2i = (const float*)d_in[17];
    const float* b2r = (const float*)d_in[18];
    const float* b2i = (const float*)d_in[19];

    float* xr = (float*)d_out;
    float* xi = xr + ND;

    unsigned *Nsp, *Qsp, *KPsp, *VPsp, *Dsp, *Osp, *Hsp;
    unsigned *sWq, *sWk, *sWv, *sWo, *sW1r, *sW1i, *sW2r, *sW2i;
    float *KVf, *PSUM;
    cudaGetSymbolAddress((void**)&Nsp, g_Nsp);
    cudaGetSymbolAddress((void**)&Qsp, g_Qsp);
    cudaGetSymbolAddress((void**)&KPsp, g_KPsp);
    cudaGetSymbolAddress((void**)&VPsp, g_VPsp);
    cudaGetSymbolAddress((void**)&Dsp, g_Dsp);
    cudaGetSymbolAddress((void**)&Osp, g_Osp);
    cudaGetSymbolAddress((void**)&Hsp, g_Hsp);
    cudaGetSymbolAddress((void**)&KVf, g_KVf);
    cudaGetSymbolAddress((void**)&PSUM, g_PSUM);
    cudaGetSymbolAddress((void**)&sWq, g_Wq);
    cudaGetSymbolAddress((void**)&sWk, g_Wk);
    cudaGetSymbolAddress((void**)&sWv, g_Wv);
    cudaGetSymbolAddress((void**)&sWo, g_Wo);
    cudaGetSymbolAddress((void**)&sW1r, g_W1r);
    cudaGetSymbolAddress((void**)&sW1i, g_W1i);
    cudaGetSymbolAddress((void**)&sW2r, g_W2r);
    cudaGetSymbolAddress((void**)&sW2i, g_W2i);

    cudaMemcpyAsync(xr, x_real, ND * sizeof(float), cudaMemcpyDeviceToDevice, 0);
    cudaMemcpyAsync(xi, x_imag, ND * sizeof(float), cudaMemcpyDeviceToDevice, 0);

    // ---- pre-split + transpose weights (TB layout)
    // QKV/O: perdepth=131072, block stride PQ=262144, launch 2*perdepth threads.
    // FFN:   perdepth=524288, block stride PF=1048576, launch 2*perdepth threads.
    const long long PQ = 262144, PF = 1048576;
    {
        conv_TB<<<(int)((PQ + 255) / 256), 256>>>(Wq, sWq, sWq + PQ, nullptr, nullptr, 256, 512);
        conv_TB<<<(int)((PQ + 255) / 256), 256>>>(Wk, sWk, sWk + PQ, nullptr, nullptr, 256, 512);
        conv_TB<<<(int)((PQ + 255) / 256), 256>>>(Wv, sWv, sWv + PQ, nullptr, nullptr, 256, 512);
        conv_TB<<<(int)((PQ + 255) / 256), 256>>>(Wout, sWo, sWo + PQ, nullptr, nullptr, 256, 512);
        conv_TB<<<(int)((PF + 255) / 256), 256>>>(W1r, sW1r, sW1r + PF, nullptr, nullptr, 256, 2048);
        conv_TB<<<(int)((PF + 255) / 256), 256>>>(W1i, sW1i, sW1i + PF, sW1i + 2 * PF, sW1i + 3 * PF, 256, 2048);
        conv_TB<<<(int)((PF + 255) / 256), 256>>>(W2r, sW2r, sW2r + PF, nullptr, nullptr, 1024, 512);
        conv_TB<<<(int)((PF + 255) / 256), 256>>>(W2i, sW2i, sW2i + PF, sW2i + 2 * PF, sW2i + 3 * PF, 1024, 512);
    }

    for (int d = 0; d < 2; d++) {
        const long long oq = (long long)d * 131072;   // perdepth u32 (QKV/O)
        const long long of = (long long)d * 524288;   // perdepth u32 (FFN)
        const float* bq_d = bq + (size_t)d * D_MODEL;
        const float* bk_d = bk + (size_t)d * D_MODEL;
        const float* bv_d = bv + (size_t)d * D_MODEL;
        const float* pk_d = pk + (size_t)d * N_TOK * K_LR;
        const float* pv_d = pv + (size_t)d * N_TOK * K_LR;
        const float* bo_d = bout + (size_t)d * D_MODEL;
        const float* b1r_d = b1r + (size_t)d * D_FF;
        const float* b1i_d = b1i + (size_t)d * D_FF;
        const float* b2r_d = b2r + (size_t)d * D_MODEL;
        const float* b2i_d = b2i + (size_t)d * D_MODEL;

        // ---- LN1 -> Nsp
        cln_kernel<<<N_TOK, 512>>>(xr, xi, Nsp);

        // ---- QKV (z=2 over r/i)
        gemmSP(Nsp, Nsp + NDH, nullptr, nullptr,
               sWq + oq, sWq + PQ + oq, nullptr, nullptr, nullptr, nullptr,
               nullptr, Qsp, Qsp + NDH, bq_d, nullptr,
               N_TOK, D_MODEL, D_MODEL, 256, 256, 512,
               2 * NDH, 0, 2 * NDH, 0, 2, 1, 1.f, 0.f, 0);
        gemmSP(Nsp, Nsp + NDH, nullptr, nullptr,
               sWk + oq, sWk + PQ + oq, nullptr, nullptr, nullptr, nullptr,
               KVf, nullptr, nullptr, bk_d, nullptr,
               N_TOK, D_MODEL, D_MODEL, 256, 256, 512,
               2 * NDH, 0, ND, 0, 2, 1, 1.f, 0.f, 0);
        gemmSP(Nsp, Nsp + NDH, nullptr, nullptr,
               sWv + oq, sWv + PQ + oq, nullptr, nullptr, nullptr, nullptr,
               KVf + 2 * ND, nullptr, nullptr, bv_d, nullptr,
               N_TOK, D_MODEL, D_MODEL, 256, 256, 512,
               2 * NDH, 0, ND, 0, 2, 1, 1.f, 0.f, 0);

        // ---- low-rank projections -> split KP (pairs along D) / VP (TB)
        {
            dim3 g(D_MODEL / 128, K_LR / 128, 4 * NSPLIT);
            proj_splitk_tc<<<g, 256>>>(pk_d, pv_d, KVf, PSUM);
            proj_reduce_sp<<<(int)((4 * KDH + 255) / 256), 256>>>(PSUM, KPsp, VPsp);
        }

        // ---- complex dots -> Dsp. z = 8 heads x 2 parts.
        gemmSP(Qsp, Qsp + NDH, Qsp + 2 * NDH, Qsp + 3 * NDH,
               KPsp, KPsp + KDH, KPsp + 2 * KDH, KPsp + 3 * KDH,
               KPsp + 4 * KDH, KPsp + 5 * KDH,
               nullptr, Dsp, Dsp + HNKH, nullptr, nullptr,
               N_TOK, K_LR, DHEAD, 256, 256, 256,
               32, 32, NKH, 2 * HNKH, H_HEADS, 2, ATTN_SCALE, 0.f, 0);

        // ---- complex attn out -> Osp. z = 8 heads x 2 parts.
        gemmSP(Dsp, Dsp + HNKH, Dsp + 2 * HNKH, Dsp + 3 * HNKH,
               VPsp, VPsp + KDH, VPsp + 2 * KDH, VPsp + 3 * KDH,
               VPsp + 4 * KDH, VPsp + 5 * KDH,
               nullptr, Osp, Osp + NDH, nullptr, nullptr,
               N_TOK, DHEAD, K_LR, 128, 128, 512,
               NKH, 8192, 32, 2 * NDH, H_HEADS, 2, 1.f, 0.f, 0);

        // ---- output projection + residual (fp32). z=2 over r/i.
        gemmSP(Osp, Osp + NDH, nullptr, nullptr,
               sWo + oq, sWo + PQ + oq, nullptr, nullptr, nullptr, nullptr,
               xr, nullptr, nullptr, bo_d, nullptr,
               N_TOK, D_MODEL, D_MODEL, 256, 256, 512,
               2 * NDH, 0, ND, 0, 2, 1, 1.f, 1.f, 0);

        // ---- LN2 -> Nsp
        cln_kernel<<<N_TOK, 512>>>(xr, xi, Nsp);

        // ---- FFN1 (+relu) -> Hsp. z = 2 parts.
        gemmSP(Nsp, Nsp + NDH, Nsp + 2 * NDH, Nsp + 3 * NDH,
               sW1r + of, sW1r + PF + of, sW1i + of, sW1i + PF + of,
               sW1i + 2 * PF + of, sW1i + 3 * PF + of,
               nullptr, Hsp, Hsp + NFFH, b1r_d, b1i_d,
               N_TOK, D_FF, D_MODEL, 256, 256, 2048,
               0, 0, 0, 2 * NFFH, 1, 2, 1.f, 0.f, 1);

        // ---- FFN2 + residual (fp32). z = 2 parts.
        gemmSP(Hsp, Hsp + NFFH, Hsp + 2 * NFFH, Hsp + 3 * NFFH,
               sW2r + of, sW2r + PF + of, sW2i + of, sW2i + PF + of,
               sW2i + 2 * PF + of, sW2i + 3 * PF + of,
               xr, nullptr, nullptr, b2r_d, b2i_d,
               N_TOK, D_MODEL, D_FF, 1024, 1024, 512,
               0, 0, 0, ND, 1, 2, 1.f, 1.f, 0);
    }
}